// round 3
// baseline (speedup 1.0000x reference)
#include <cuda_runtime.h>

#define BATCH 2048
#define TSEQ  100
#define DVAR  51
#define HID   128
#define G4    512
#define RPB   14      // batch rows per block
#define NBLK  147
#define NTHR  512

#define KIN0  52              // padded input width for layers 0/3 (51 -> 52, even)
#define XSTR  (KIN0*2)        // 104 floats per row-pair in x buffer
#define HSTR  (HID*2)         // 256 floats per row-pair in h/c buffers
#define GSTR  (G4*2)          // 1024 floats per row-pair in gate buffer

// rows per layer in packed transposed weights: Kin + 128
#define R_L0  (KIN0 + HID)    // 180
#define R_L1  (HID + HID)     // 256
#define OFF0  0
#define OFF1  (R_L0*G4)
#define OFF2  ((R_L0 + R_L1)*G4)
#define OFF3  ((R_L0 + 2*R_L1)*G4)
#define OFF4  ((2*R_L0 + 2*R_L1)*G4)
#define OFF5  ((2*R_L0 + 3*R_L1)*G4)
#define WTOT  ((2*R_L0 + 4*R_L1)*G4)       /* 1384*512 */

#define SMEM_FLOATS (7*XSTR + 6*7*HSTR + 7*GSTR)   /* 728 + 10752 + 7168 = 18648 */
#define SMEM_BYTES  (SMEM_FLOATS*4)

// Packed transposed weights, all 6 layers contiguous + 8-row prefetch pad.
__device__ float g_wt[WTOT + 8*G4];
// fW^T padded: [128][64], cols >= 51 zero
__device__ float g_fwt[128*64];

typedef unsigned long long ull;

__device__ __forceinline__ ull dup2(float x) {
    ull r; asm("mov.b64 %0, {%1, %1};" : "=l"(r) : "f"(x)); return r;
}
__device__ __forceinline__ void fma2(ull& d, ull a, ull b) {
    asm("fma.rn.f32x2 %0, %1, %2, %0;" : "+l"(d) : "l"(a), "l"(b));
}
__device__ __forceinline__ float sigf(float x) {
    return __fdividef(1.0f, 1.0f + __expf(-x));
}

// ---------------------------------------------------------------------------
// Prep: pack transposed weights (and fW) into g_wt / g_fwt
// ---------------------------------------------------------------------------
__global__ void prep_kernel(
    const float* w0, const float* u0, const float* w1, const float* u1,
    const float* w2, const float* u2, const float* w3, const float* u3,
    const float* w4, const float* u4, const float* w5, const float* u5,
    const float* fW)
{
    const float* WIH[6] = {w0, w1, w2, w3, w4, w5};
    const float* WHH[6] = {u0, u1, u2, u3, u4, u5};
    const int total = WTOT + 8*G4 + 128*64;
    for (int idx = blockIdx.x*blockDim.x + threadIdx.x; idx < total;
         idx += gridDim.x*blockDim.x) {
        if (idx < WTOT) {
            int row = idx >> 9, j = idx & 511;
            int l, base, kin, din;
            if      (row < R_L0)              { l=0; base=0;               kin=KIN0; din=DVAR; }
            else if (row < R_L0 + R_L1)       { l=1; base=R_L0;            kin=HID;  din=HID;  }
            else if (row < R_L0 + 2*R_L1)     { l=2; base=R_L0+R_L1;       kin=HID;  din=HID;  }
            else if (row < 2*R_L0 + 2*R_L1)   { l=3; base=R_L0+2*R_L1;     kin=KIN0; din=DVAR; }
            else if (row < 2*R_L0 + 3*R_L1)   { l=4; base=2*R_L0+2*R_L1;   kin=HID;  din=HID;  }
            else                              { l=5; base=2*R_L0+3*R_L1;   kin=HID;  din=HID;  }
            int k = row - base;
            float v;
            if (k < kin) v = (k < din) ? WIH[l][j*din + k] : 0.0f;
            else         v = WHH[l][j*HID + (k - kin)];
            g_wt[idx] = v;
        } else if (idx < WTOT + 8*G4) {
            g_wt[idx] = 0.0f;                 // prefetch pad
        } else {
            int r2 = idx - (WTOT + 8*G4);
            int u = r2 >> 6;
            int d = r2 & 63;
            g_fwt[r2] = (d < DVAR) ? fW[d*HID + u] : 0.0f;
        }
    }
}

// ---------------------------------------------------------------------------
// GEMM partial: acc[7 row-pairs] += x[k][rows] * W^T[k][j] for this thread's
// single column j. x layout: [rp][k][2] -> one LDS.128 broadcast covers 2 k's.
// Weight stream register-pipelined 8 k's deep (covers L2 latency).
// ---------------------------------------------------------------------------
template<int K, int RSTR>
__device__ __forceinline__ void gpart(const float* __restrict__ w,
                                      const float* xin, ull* acc, int j)
{
    const float* wp = w + j;
    float A[4], B[4];
#pragma unroll
    for (int q = 0; q < 4; q++) {
        A[q] = wp[q*G4];
        B[q] = wp[(4 + q)*G4];
    }
#pragma unroll 2
    for (int kg = 0; kg < K/4; kg++) {
        float N[4];
#pragma unroll
        for (int q = 0; q < 4; q++)
            N[q] = wp[(kg*4 + 8 + q)*G4];      // runs into pad / next layer: safe
#pragma unroll
        for (int s = 0; s < 2; s++) {
            ull wa = dup2(A[2*s]);
            ull wb = dup2(A[2*s + 1]);
            const float* xk = xin + (kg*4 + 2*s)*2;
#pragma unroll
            for (int rp = 0; rp < 7; rp++) {
                ulonglong2 xp = *(const ulonglong2*)(xk + rp*RSTR); // LDS.128 bcast
                fma2(acc[rp], xp.x, wa);
                fma2(acc[rp], xp.y, wb);
            }
        }
#pragma unroll
        for (int q = 0; q < 4; q++) { A[q] = B[q]; B[q] = N[q]; }
    }
}

// ---------------------------------------------------------------------------
// One LSTM cell for the block's 14 rows. Thread owns gate column j = tid.
// ---------------------------------------------------------------------------
template<int KIN, int RSTR>
__device__ __noinline__ void cell(const float* __restrict__ wt,
                                  const float* __restrict__ bias,
                                  const float* xin, float* h, float* c,
                                  float* gt, int tid)
{
    ull acc[7];
    {
        ull b2 = dup2(bias[tid]);
#pragma unroll
        for (int rp = 0; rp < 7; rp++) acc[rp] = b2;
    }
    gpart<KIN, RSTR>(wt, xin, acc, tid);
    gpart<HID, HSTR>(wt + KIN*G4, h, acc, tid);

#pragma unroll
    for (int rp = 0; rp < 7; rp++)
        *(ull*)(gt + rp*GSTR + tid*2) = acc[rp];   // STS.64, conflict-free
    __syncthreads();

    // elementwise: 7 rp x 128 units, float2 per item = 896 items
#pragma unroll
    for (int it = 0; it < 2; it++) {
        int idx = tid + it*NTHR;
        if (idx < 896) {
            int u  = idx & 127;
            int rp = idx >> 7;
            float2 gi = *(float2*)(gt + rp*GSTR + u*2);
            float2 gf = *(float2*)(gt + rp*GSTR + (u + 128)*2);
            float2 gg = *(float2*)(gt + rp*GSTR + (u + 256)*2);
            float2 go = *(float2*)(gt + rp*GSTR + (u + 384)*2);
            float2 cc = *(float2*)(c + rp*HSTR + u*2);
            float2 cn, hn;
            cn.x = sigf(gf.x)*cc.x + sigf(gi.x)*tanhf(gg.x);
            cn.y = sigf(gf.y)*cc.y + sigf(gi.y)*tanhf(gg.y);
            hn.x = sigf(go.x)*tanhf(cn.x);
            hn.y = sigf(go.y)*tanhf(cn.y);
            *(float2*)(c + rp*HSTR + u*2) = cn;
            *(float2*)(h + rp*HSTR + u*2) = hn;
        }
    }
    __syncthreads();
}

// ---------------------------------------------------------------------------
// Main persistent kernel: each block owns 14 batch rows, runs full enc+dec.
// ---------------------------------------------------------------------------
__global__ void __launch_bounds__(NTHR, 1) lstm_main(
    const float* __restrict__ src,
    const float* __restrict__ eb0, const float* __restrict__ eb1,
    const float* __restrict__ eb2,
    const float* __restrict__ db0, const float* __restrict__ db1,
    const float* __restrict__ db2,
    const float* __restrict__ fb,
    float* __restrict__ out)
{
    extern __shared__ float sm[];
    float* xt = sm;                        // [7][KIN0][2]
    float* h0 = xt + 7*XSTR;               // [7][128][2] each
    float* h1 = h0 + 7*HSTR;
    float* h2 = h1 + 7*HSTR;
    float* c0 = h2 + 7*HSTR;
    float* c1 = c0 + 7*HSTR;
    float* c2 = c1 + 7*HSTR;
    float* gt = c2 + 7*HSTR;               // [7][512][2]

    const int tid = threadIdx.x;
    const int b0  = blockIdx.x * RPB;

    for (int i = tid; i < SMEM_FLOATS; i += NTHR) sm[i] = 0.0f;
    __syncthreads();

    // ----------------- encoder -----------------
    for (int t = 0; t < TSEQ; t++) {
        for (int i = tid; i < DVAR*RPB; i += NTHR) {
            int r = i / DVAR;
            int k = i - r*DVAR;
            int b = b0 + r; if (b >= BATCH) b = BATCH - 1;
            xt[(r >> 1)*XSTR + k*2 + (r & 1)] = src[(b*TSEQ + t)*DVAR + k];
        }
        __syncthreads();
        cell<KIN0, XSTR>(g_wt + OFF0, eb0, xt, h0, c0, gt, tid);
        cell<HID,  HSTR>(g_wt + OFF1, eb1, h0, h1, c1, gt, tid);
        cell<HID,  HSTR>(g_wt + OFF2, eb2, h1, h2, c2, gt, tid);
    }

    // ----------------- decoder -----------------
    for (int i = tid; i < 7*XSTR; i += NTHR) xt[i] = 0.0f;   // x0 = zeros
    __syncthreads();

    for (int t = 0; t < TSEQ; t++) {
        cell<KIN0, XSTR>(g_wt + OFF3, db0, xt, h0, c0, gt, tid);
        cell<HID,  HSTR>(g_wt + OFF4, db1, h0, h1, c1, gt, tid);
        cell<HID,  HSTR>(g_wt + OFF5, db2, h1, h2, c2, gt, tid);

        // head: pred[r][d] = h2[r] . fW[d] + fb[d]; write out (reversed) + feedback
        {
            int d  = tid & 63;
            int rg = tid >> 6;                 // 0..7 ; rows rg and rg+8
            float fbv = (d < DVAR) ? fb[d] : 0.0f;
            float a0 = fbv, a1 = fbv;
            int r0 = rg, r1 = rg + 8;
#pragma unroll 4
            for (int u = 0; u < HID; u++) {
                float wv = g_fwt[(u << 6) + d];
                float x0 = h2[(r0 >> 1)*HSTR + u*2 + (r0 & 1)];
                float x1 = h2[(r1 >> 1)*HSTR + u*2 + (r1 & 1)];   // rp<=7: reads c0, discarded
                a0 += x0*wv;
                a1 += x1*wv;
            }
            if (d < DVAR) {
                xt[(r0 >> 1)*XSTR + d*2 + (r0 & 1)] = a0;
                int bb = b0 + r0;
                if (bb < BATCH)
                    out[(bb*TSEQ + (TSEQ - 1 - t))*DVAR + d] = a0;
                if (r1 < RPB) {
                    xt[(r1 >> 1)*XSTR + d*2 + (r1 & 1)] = a1;
                    int bb1 = b0 + r1;
                    if (bb1 < BATCH)
                        out[(bb1*TSEQ + (TSEQ - 1 - t))*DVAR + d] = a1;
                }
            }
        }
        __syncthreads();
    }
}

// ---------------------------------------------------------------------------
// Input order: 0 src, then (eW,eU,eb)x3, (dW,dU,db)x3, fW, fb
// ---------------------------------------------------------------------------
extern "C" void kernel_launch(void* const* d_in, const int* in_sizes, int n_in,
                              void* d_out, int out_size)
{
    const float* src = (const float*)d_in[0];
    const float* eW0 = (const float*)d_in[1];
    const float* eU0 = (const float*)d_in[2];
    const float* eb0 = (const float*)d_in[3];
    const float* eW1 = (const float*)d_in[4];
    const float* eU1 = (const float*)d_in[5];
    const float* eb1 = (const float*)d_in[6];
    const float* eW2 = (const float*)d_in[7];
    const float* eU2 = (const float*)d_in[8];
    const float* eb2 = (const float*)d_in[9];
    const float* dW0 = (const float*)d_in[10];
    const float* dU0 = (const float*)d_in[11];
    const float* db0 = (const float*)d_in[12];
    const float* dW1 = (const float*)d_in[13];
    const float* dU1 = (const float*)d_in[14];
    const float* db1 = (const float*)d_in[15];
    const float* dW2 = (const float*)d_in[16];
    const float* dU2 = (const float*)d_in[17];
    const float* db2 = (const float*)d_in[18];
    const float* fW  = (const float*)d_in[19];
    const float* fb  = (const float*)d_in[20];
    float* out = (float*)d_out;

    cudaFuncSetAttribute(lstm_main, cudaFuncAttributeMaxDynamicSharedMemorySize,
                         SMEM_BYTES);

    prep_kernel<<<1024, 256>>>(eW0, eU0, eW1, eU1, eW2, eU2,
                               dW0, dU0, dW1, dU1, dW2, dU2, fW);
    lstm_main<<<NBLK, NTHR, SMEM_BYTES>>>(src, eb0, eb1, eb2,
                                          db0, db1, db2, fb, out);
}

// round 4
// speedup vs baseline: 1.3739x; 1.3739x over previous
#include <cuda_runtime.h>

#define BATCH 2048
#define TSEQ  100
#define DVAR  51
#define HID   128
#define G4    512
#define RPB   14      // batch rows per block
#define XTS   18      // padded transposed stride (rows dim)
#define WSZ   (256*512)
#define NBLK  147
#define NTHR  512
// x + 3h + 3c (7 x 128 x 18) + two gate partial buffers (2 x 512 x 18)
#define SMEM_FLOATS (7*128*XTS + 2*512*XTS)
#define SMEM_BYTES  (SMEM_FLOATS*4)

// Transposed weights: per layer [256][512]; rows [0,128) = Wih^T (zero-padded),
// rows [128,256) = Whh^T. 8-row pad for unguarded prefetch.
__device__ float g_wt[6*WSZ + 8*G4];
// fW^T padded: [128][64], cols >= 51 zero
__device__ float g_fwt[128*64];

typedef unsigned long long ull;

__device__ __forceinline__ ull dup2(float x) {
    ull r; asm("mov.b64 %0, {%1, %1};" : "=l"(r) : "f"(x)); return r;
}
__device__ __forceinline__ void fma2(ull& d, ull a, ull b) {
    asm("fma.rn.f32x2 %0, %1, %2, %0;" : "+l"(d) : "l"(a), "l"(b));
}
__device__ __forceinline__ float sigf(float x) {
    return __fdividef(1.0f, 1.0f + __expf(-x));
}

// ---------------------------------------------------------------------------
// Prep: transpose all LSTM weights (and fW) into g_wt / g_fwt
// ---------------------------------------------------------------------------
__global__ void prep_kernel(
    const float* w0, const float* u0, const float* w1, const float* u1,
    const float* w2, const float* u2, const float* w3, const float* u3,
    const float* w4, const float* u4, const float* w5, const float* u5,
    const float* fW)
{
    const float* WIH[6] = {w0, w1, w2, w3, w4, w5};
    const float* WHH[6] = {u0, u1, u2, u3, u4, u5};
    const int total = 6*WSZ + 8*G4 + 128*64;
    for (int idx = blockIdx.x*blockDim.x + threadIdx.x; idx < total;
         idx += gridDim.x*blockDim.x) {
        if (idx < 6*WSZ) {
            int layer = idx / WSZ;
            int rem   = idx - layer*WSZ;
            int k = rem >> 9;
            int j = rem & 511;
            int din = (layer == 0 || layer == 3) ? DVAR : HID;
            float v;
            if (k < 128) v = (k < din) ? WIH[layer][j*din + k] : 0.0f;
            else         v = WHH[layer][j*HID + (k - 128)];
            g_wt[idx] = v;
        } else if (idx < 6*WSZ + 8*G4) {
            g_wt[idx] = 0.0f;                 // prefetch pad
        } else {
            int r2 = idx - (6*WSZ + 8*G4);
            int u = r2 >> 6;
            int d = r2 & 63;
            g_fwt[r2] = (d < DVAR) ? fW[d*HID + u] : 0.0f;
        }
    }
}

// ---------------------------------------------------------------------------
// GEMM partial over a k-range: acc[2 cols][7 row-pairs] += x[k][.] * W^T[k][.]
// x in smem [k][XTS], LDS.64 broadcast per row-pair. Weight stream register-
// pipelined 8 k's deep from L2.
// ---------------------------------------------------------------------------
template<int K>
__device__ __forceinline__ void gpart(const float* __restrict__ w,
                                      const float* xin,
                                      ull* acc0, ull* acc1, int j0)
{
    const float* wp = w + j0;
    float2 A[4], B[4];
#pragma unroll
    for (int q = 0; q < 4; q++) {
        A[q] = *(const float2*)(wp + q*G4);
        B[q] = *(const float2*)(wp + (4 + q)*G4);
    }
#pragma unroll 2
    for (int kg = 0; kg < K/4; kg++) {
        float2 N[4];
#pragma unroll
        for (int q = 0; q < 4; q++)
            N[q] = *(const float2*)(wp + (kg*4 + 8 + q)*G4);  // pad-safe
#pragma unroll
        for (int q = 0; q < 4; q++) {
            const int k = kg*4 + q;
            ull wa = dup2(A[q].x);
            ull wb = dup2(A[q].y);
            const float* xk = xin + k*XTS;
#pragma unroll
            for (int rp = 0; rp < 7; rp++) {
                ull xp = *(const ull*)(xk + 2*rp);    // LDS.64 broadcast
                fma2(acc0[rp], xp, wa);
                fma2(acc1[rp], xp, wb);
            }
        }
#pragma unroll
        for (int q = 0; q < 4; q++) { A[q] = B[q]; B[q] = N[q]; }
    }
}

// ---------------------------------------------------------------------------
// One LSTM cell, k-split across two 256-thread sets.
//   set 0 (tid<256): k in first halves (with bias), writes gtA
//   set 1          : k in second halves (zero init), writes gtB
// Elementwise sums gtA+gtB.
// ---------------------------------------------------------------------------
template<int KIN>
__device__ __noinline__ void cell(const float* __restrict__ wt,
                                  const float* __restrict__ bias,
                                  const float* xin, float* h, float* c,
                                  float* gtA, float* gtB, int tid)
{
    const int set = tid >> 8;            // 0 or 1
    const int j0  = (tid & 255) << 1;
    constexpr int KH = KIN/2;

    ull acc0[7], acc1[7];
    if (set == 0) {
        float2 bv = *(const float2*)(bias + j0);
        ull d0 = dup2(bv.x), d1 = dup2(bv.y);
#pragma unroll
        for (int rp = 0; rp < 7; rp++) { acc0[rp] = d0; acc1[rp] = d1; }
    } else {
#pragma unroll
        for (int rp = 0; rp < 7; rp++) { acc0[rp] = 0ull; acc1[rp] = 0ull; }
    }

    gpart<KH>(wt + set*KH*G4,          xin + set*KH*XTS, acc0, acc1, j0);
    gpart<64>(wt + (128 + set*64)*G4,  h   + set*64*XTS, acc0, acc1, j0);

    float* gt = set ? gtB : gtA;
#pragma unroll
    for (int rp = 0; rp < 7; rp++) {
        *(ull*)(gt + (j0    )*XTS + 2*rp) = acc0[rp];
        *(ull*)(gt + (j0 + 1)*XTS + 2*rp) = acc1[rp];
    }
    __syncthreads();

    // elementwise: 14 rows x 128 units = 1792 items over 512 threads
#pragma unroll
    for (int it = 0; it < 4; it++) {
        int idx = tid + it*NTHR;
        if (idx < 1792) {
            int u = idx & 127;
            int r = idx >> 7;
            float gi = gtA[(u      )*XTS + r] + gtB[(u      )*XTS + r];
            float gf = gtA[(u + 128)*XTS + r] + gtB[(u + 128)*XTS + r];
            float gg = gtA[(u + 256)*XTS + r] + gtB[(u + 256)*XTS + r];
            float go = gtA[(u + 384)*XTS + r] + gtB[(u + 384)*XTS + r];
            float cv = sigf(gf) * c[u*XTS + r] + sigf(gi) * tanhf(gg);
            c[u*XTS + r] = cv;
            h[u*XTS + r] = sigf(go) * tanhf(cv);
        }
    }
    __syncthreads();
}

// ---------------------------------------------------------------------------
// Main persistent kernel: each block owns 14 batch rows, runs full enc+dec.
// ---------------------------------------------------------------------------
__global__ void __launch_bounds__(NTHR, 1) lstm_main(
    const float* __restrict__ src,
    const float* __restrict__ eb0, const float* __restrict__ eb1,
    const float* __restrict__ eb2,
    const float* __restrict__ db0, const float* __restrict__ db1,
    const float* __restrict__ db2,
    const float* __restrict__ fb,
    float* __restrict__ out)
{
    extern __shared__ float sm[];
    float* xt  = sm;                        // [128][XTS]
    float* h0  = sm + 1*128*XTS;
    float* h1  = sm + 2*128*XTS;
    float* h2  = sm + 3*128*XTS;
    float* c0  = sm + 4*128*XTS;
    float* c1  = sm + 5*128*XTS;
    float* c2  = sm + 6*128*XTS;
    float* gtA = sm + 7*128*XTS;            // [512][XTS]
    float* gtB = gtA + 512*XTS;             // [512][XTS]

    const int tid = threadIdx.x;
    const int b0  = blockIdx.x * RPB;

    for (int i = tid; i < SMEM_FLOATS; i += NTHR) sm[i] = 0.0f;
    __syncthreads();

    // ----------------- encoder -----------------
    for (int t = 0; t < TSEQ; t++) {
        for (int i = tid; i < DVAR*RPB; i += NTHR) {
            int r = i / DVAR;
            int k = i - r*DVAR;
            int b = b0 + r; if (b >= BATCH) b = BATCH - 1;
            xt[k*XTS + r] = src[(b*TSEQ + t)*DVAR + k];
        }
        __syncthreads();
        cell<64 >(g_wt + 0*WSZ, eb0, xt, h0, c0, gtA, gtB, tid);
        cell<128>(g_wt + 1*WSZ, eb1, h0, h1, c1, gtA, gtB, tid);
        cell<128>(g_wt + 2*WSZ, eb2, h1, h2, c2, gtA, gtB, tid);
    }

    // ----------------- decoder -----------------
    for (int i = tid; i < 128*XTS; i += NTHR) xt[i] = 0.0f;   // x0 = zeros
    __syncthreads();

    for (int t = 0; t < TSEQ; t++) {
        cell<64 >(g_wt + 3*WSZ, db0, xt, h0, c0, gtA, gtB, tid);
        cell<128>(g_wt + 4*WSZ, db1, h0, h1, c1, gtA, gtB, tid);
        cell<128>(g_wt + 5*WSZ, db2, h1, h2, c2, gtA, gtB, tid);

        // head: pred[r][d] = h2[r] . fW[d] + fb[d]; write out (reversed) + feedback
        {
            int d  = tid & 63;
            int rg = tid >> 6;                 // 0..7 ; rows rg and rg+8
            float fbv = (d < DVAR) ? fb[d] : 0.0f;
            float a0 = fbv, a1 = fbv;
            int r0 = rg, r1 = rg + 8;
#pragma unroll 4
            for (int u = 0; u < HID; u++) {
                float wv = g_fwt[(u << 6) + d];
                a0 += h2[u*XTS + r0] * wv;
                a1 += h2[u*XTS + r1] * wv;     // r1<=15 < XTS: in-bounds, guarded below
            }
            if (d < DVAR) {
                xt[d*XTS + r0] = a0;
                int bb = b0 + r0;
                if (bb < BATCH)
                    out[(bb*TSEQ + (TSEQ - 1 - t))*DVAR + d] = a0;
                if (r1 < RPB) {
                    xt[d*XTS + r1] = a1;
                    int bb1 = b0 + r1;
                    if (bb1 < BATCH)
                        out[(bb1*TSEQ + (TSEQ - 1 - t))*DVAR + d] = a1;
                }
            }
        }
        __syncthreads();
    }
}

// ---------------------------------------------------------------------------
// Input order: 0 src, then (eW,eU,eb)x3, (dW,dU,db)x3, fW, fb
// ---------------------------------------------------------------------------
extern "C" void kernel_launch(void* const* d_in, const int* in_sizes, int n_in,
                              void* d_out, int out_size)
{
    const float* src = (const float*)d_in[0];
    const float* eW0 = (const float*)d_in[1];
    const float* eU0 = (const float*)d_in[2];
    const float* eb0 = (const float*)d_in[3];
    const float* eW1 = (const float*)d_in[4];
    const float* eU1 = (const float*)d_in[5];
    const float* eb1 = (const float*)d_in[6];
    const float* eW2 = (const float*)d_in[7];
    const float* eU2 = (const float*)d_in[8];
    const float* eb2 = (const float*)d_in[9];
    const float* dW0 = (const float*)d_in[10];
    const float* dU0 = (const float*)d_in[11];
    const float* db0 = (const float*)d_in[12];
    const float* dW1 = (const float*)d_in[13];
    const float* dU1 = (const float*)d_in[14];
    const float* db1 = (const float*)d_in[15];
    const float* dW2 = (const float*)d_in[16];
    const float* dU2 = (const float*)d_in[17];
    const float* db2 = (const float*)d_in[18];
    const float* fW  = (const float*)d_in[19];
    const float* fb  = (const float*)d_in[20];
    float* out = (float*)d_out;

    cudaFuncSetAttribute(lstm_main, cudaFuncAttributeMaxDynamicSharedMemorySize,
                         SMEM_BYTES);

    prep_kernel<<<1024, 256>>>(eW0, eU0, eW1, eU1, eW2, eU2,
                               dW0, dU0, dW1, dU1, dW2, dU2, fW);
    lstm_main<<<NBLK, NTHR, SMEM_BYTES>>>(src, eb0, eb1, eb2,
                                          db0, db1, db2, fb, out);
}

// round 5
// speedup vs baseline: 1.4935x; 1.0870x over previous
#include <cuda_runtime.h>

#define BATCH 2048
#define TSEQ  100
#define DVAR  51
#define HID   128
#define G4    512
#define RPB   14      // batch rows per block
#define XTS   18      // padded stride for state buffers [128][XTS]
#define WSZ   (256*512)
#define NBLK  147
#define NTHR  512

// gate buffer geometry: [rp 0..6][c 0..3][t 0..127][2], c-stride padded
#define GB_C   264                 /* floats per c-slot (128*2 + 8 pad) */
#define GB_RP  (4*GB_C)            /* 1056 floats per rp */
#define GBUF   (7*GB_RP)           /* one set's buffer: 7392 floats */

#define SMEM_FLOATS (7*128*XTS + 4*GBUF)   /* 16128 + 29568 = 45696 */
#define SMEM_BYTES  (SMEM_FLOATS*4)

// Transposed weights: per layer [256][512]; rows [0,128) = Wih^T (zero-padded),
// rows [128,256) = Whh^T. 8-row pad for unguarded prefetch.
__device__ float g_wt[6*WSZ + 8*G4];
// fW^T padded: [128][64], cols >= 51 zero
__device__ float g_fwt[128*64];

typedef unsigned long long ull;

__device__ __forceinline__ ull dup2(float x) {
    ull r; asm("mov.b64 %0, {%1, %1};" : "=l"(r) : "f"(x)); return r;
}
__device__ __forceinline__ void fma2(ull& d, ull a, ull b) {
    asm("fma.rn.f32x2 %0, %1, %2, %0;" : "+l"(d) : "l"(a), "l"(b));
}
__device__ __forceinline__ float sigf(float x) {
    return __fdividef(1.0f, 1.0f + __expf(-x));
}
__device__ __forceinline__ float tanhff(float x) {
    float e = __expf(2.0f * x);
    return 1.0f - __fdividef(2.0f, e + 1.0f);
}

// ---------------------------------------------------------------------------
// Prep: transpose all LSTM weights (and fW) into g_wt / g_fwt
// ---------------------------------------------------------------------------
__global__ void prep_kernel(
    const float* w0, const float* u0, const float* w1, const float* u1,
    const float* w2, const float* u2, const float* w3, const float* u3,
    const float* w4, const float* u4, const float* w5, const float* u5,
    const float* fW)
{
    const float* WIH[6] = {w0, w1, w2, w3, w4, w5};
    const float* WHH[6] = {u0, u1, u2, u3, u4, u5};
    const int total = 6*WSZ + 8*G4 + 128*64;
    for (int idx = blockIdx.x*blockDim.x + threadIdx.x; idx < total;
         idx += gridDim.x*blockDim.x) {
        if (idx < 6*WSZ) {
            int layer = idx / WSZ;
            int rem   = idx - layer*WSZ;
            int k = rem >> 9;
            int j = rem & 511;
            int din = (layer == 0 || layer == 3) ? DVAR : HID;
            float v;
            if (k < 128) v = (k < din) ? WIH[layer][j*din + k] : 0.0f;
            else         v = WHH[layer][j*HID + (k - 128)];
            g_wt[idx] = v;
        } else if (idx < 6*WSZ + 8*G4) {
            g_wt[idx] = 0.0f;                 // prefetch pad
        } else {
            int r2 = idx - (6*WSZ + 8*G4);
            int u = r2 >> 6;
            int d = r2 & 63;
            g_fwt[r2] = (d < DVAR) ? fW[d*HID + u] : 0.0f;
        }
    }
}

// ---------------------------------------------------------------------------
// GEMM partial over a k-range: acc[4 cols][7 row-pairs] += x[k][.] * W^T[k][.]
// wp = weight base + j0 (thread's 4-col base). Per k: one LDG.128 (prefetch
// 4 k's ahead), 7 LDS.64 broadcasts, 28 FFMA2.
// ---------------------------------------------------------------------------
template<int K>
__device__ __forceinline__ void gpart(const float* __restrict__ wp,
                                      const float* xin, ull* acc)
{
    float4 W[4];
#pragma unroll
    for (int q = 0; q < 4; q++) W[q] = *(const float4*)(wp + q*G4);

#pragma unroll 1
    for (int kg = 0; kg < K/4; kg++) {
#pragma unroll
        for (int q = 0; q < 4; q++) {
            const int k = kg*4 + q;
            float4 cur = W[q];
            W[q] = *(const float4*)(wp + (k + 4)*G4);   // prefetch (pad-safe)
            ull wa = dup2(cur.x);
            ull wb = dup2(cur.y);
            ull wc = dup2(cur.z);
            ull wd = dup2(cur.w);
            const float* xk = xin + k*XTS;
#pragma unroll
            for (int rp = 0; rp < 7; rp++) {
                ull xp = *(const ull*)(xk + 2*rp);      // LDS.64 broadcast
                fma2(acc[0*7 + rp], xp, wa);
                fma2(acc[1*7 + rp], xp, wb);
                fma2(acc[2*7 + rp], xp, wc);
                fma2(acc[3*7 + rp], xp, wd);
            }
        }
    }
}

// ---------------------------------------------------------------------------
// One LSTM cell, k-split across four 128-thread sets; each set covers all
// 512 gate columns (4 per thread) over K/4 k-steps, writing its own partial
// gate buffer. Elementwise sums the 4 partials.
// ---------------------------------------------------------------------------
template<int KIN>
__device__ __noinline__ void cell(const float* __restrict__ wt,
                                  const float* __restrict__ bias,
                                  const float* xin, float* h, float* c,
                                  float* gb, int tid)
{
    const int set = tid >> 7;            // 0..3
    const int t   = tid & 127;
    const int j0  = t << 2;              // 4-col base
    constexpr int KHX = KIN/4;

    ull acc[28];
    if (set == 0) {
        float4 bv = *(const float4*)(bias + j0);
#pragma unroll
        for (int rp = 0; rp < 7; rp++) {
            acc[0*7+rp] = dup2(bv.x); acc[1*7+rp] = dup2(bv.y);
            acc[2*7+rp] = dup2(bv.z); acc[3*7+rp] = dup2(bv.w);
        }
    } else {
#pragma unroll
        for (int i = 0; i < 28; i++) acc[i] = 0ull;
    }

    gpart<KHX>(wt + (set*KHX)*G4 + j0,       xin + (set*KHX)*XTS, acc);
    gpart<32 >(wt + (128 + set*32)*G4 + j0,  h   + (set*32)*XTS,  acc);

    float* gs = gb + set*GBUF;
#pragma unroll
    for (int cc = 0; cc < 4; cc++)
#pragma unroll
        for (int rp = 0; rp < 7; rp++)
            *(ull*)(gs + rp*GB_RP + cc*GB_C + t*2) = acc[cc*7 + rp]; // conflict-free STS.64
    __syncthreads();

    // elementwise: 128 units x 7 row-pairs = 896 items over 512 threads
#pragma unroll
    for (int it = 0; it < 2; it++) {
        int idx = tid + it*NTHR;
        if (idx < 896) {
            int u  = idx & 127;
            int rp = idx >> 7;
            int cb = rp*GB_RP + (u & 3)*GB_C + (u >> 2)*2;
            float2 gi = {0.f, 0.f}, gf = {0.f, 0.f}, gg = {0.f, 0.f}, go = {0.f, 0.f};
#pragma unroll
            for (int s = 0; s < 4; s++) {
                const float* g = gb + s*GBUF + cb;
                float2 a = *(const float2*)(g      );
                float2 b = *(const float2*)(g +  64);
                float2 d = *(const float2*)(g + 128);
                float2 e = *(const float2*)(g + 192);
                gi.x += a.x; gi.y += a.y;
                gf.x += b.x; gf.y += b.y;
                gg.x += d.x; gg.y += d.y;
                go.x += e.x; go.y += e.y;
            }
            float2 cc2 = *(const float2*)(c + u*XTS + 2*rp);
            float2 cn, hn;
            cn.x = sigf(gf.x)*cc2.x + sigf(gi.x)*tanhff(gg.x);
            cn.y = sigf(gf.y)*cc2.y + sigf(gi.y)*tanhff(gg.y);
            hn.x = sigf(go.x)*tanhff(cn.x);
            hn.y = sigf(go.y)*tanhff(cn.y);
            *(float2*)(c + u*XTS + 2*rp) = cn;
            *(float2*)(h + u*XTS + 2*rp) = hn;
        }
    }
    __syncthreads();
}

// ---------------------------------------------------------------------------
// Main persistent kernel: each block owns 14 batch rows, runs full enc+dec.
// ---------------------------------------------------------------------------
__global__ void __launch_bounds__(NTHR, 1) lstm_main(
    const float* __restrict__ src,
    const float* __restrict__ eb0, const float* __restrict__ eb1,
    const float* __restrict__ eb2,
    const float* __restrict__ db0, const float* __restrict__ db1,
    const float* __restrict__ db2,
    const float* __restrict__ fb,
    float* __restrict__ out)
{
    extern __shared__ float sm[];
    float* xt = sm;                        // [128][XTS]
    float* h0 = sm + 1*128*XTS;
    float* h1 = sm + 2*128*XTS;
    float* h2 = sm + 3*128*XTS;
    float* c0 = sm + 4*128*XTS;
    float* c1 = sm + 5*128*XTS;
    float* c2 = sm + 6*128*XTS;
    float* gb = sm + 7*128*XTS;            // 4 x GBUF

    const int tid = threadIdx.x;
    const int b0  = blockIdx.x * RPB;

    for (int i = tid; i < 7*128*XTS; i += NTHR) sm[i] = 0.0f;
    __syncthreads();

    // ----------------- encoder -----------------
    for (int t = 0; t < TSEQ; t++) {
        for (int i = tid; i < DVAR*RPB; i += NTHR) {
            int r = i / DVAR;
            int k = i - r*DVAR;
            int b = b0 + r; if (b >= BATCH) b = BATCH - 1;
            xt[k*XTS + r] = src[(b*TSEQ + t)*DVAR + k];
        }
        __syncthreads();
        cell<64 >(g_wt + 0*WSZ, eb0, xt, h0, c0, gb, tid);
        cell<128>(g_wt + 1*WSZ, eb1, h0, h1, c1, gb, tid);
        cell<128>(g_wt + 2*WSZ, eb2, h1, h2, c2, gb, tid);
    }

    // ----------------- decoder -----------------
    for (int i = tid; i < 128*XTS; i += NTHR) xt[i] = 0.0f;   // x0 = zeros
    __syncthreads();

    for (int t = 0; t < TSEQ; t++) {
        cell<64 >(g_wt + 3*WSZ, db0, xt, h0, c0, gb, tid);
        cell<128>(g_wt + 4*WSZ, db1, h0, h1, c1, gb, tid);
        cell<128>(g_wt + 5*WSZ, db2, h1, h2, c2, gb, tid);

        // head: pred[r][d] = h2[r] . fW[d] + fb[d]; write out (reversed) + feedback
        {
            int d  = tid & 63;
            int rg = tid >> 6;                 // 0..7 ; rows rg and rg+8
            float fbv = (d < DVAR) ? fb[d] : 0.0f;
            float a0 = fbv, a1 = fbv;
            int r0 = rg, r1 = rg + 8;
#pragma unroll 4
            for (int u = 0; u < HID; u++) {
                float wv = g_fwt[(u << 6) + d];
                a0 += h2[u*XTS + r0] * wv;
                a1 += h2[u*XTS + r1] * wv;     // r1<=15 < XTS: in-bounds, guarded below
            }
            if (d < DVAR) {
                xt[d*XTS + r0] = a0;
                int bb = b0 + r0;
                if (bb < BATCH)
                    out[(bb*TSEQ + (TSEQ - 1 - t))*DVAR + d] = a0;
                if (r1 < RPB) {
                    xt[d*XTS + r1] = a1;
                    int bb1 = b0 + r1;
                    if (bb1 < BATCH)
                        out[(bb1*TSEQ + (TSEQ - 1 - t))*DVAR + d] = a1;
                }
            }
        }
        __syncthreads();
    }
}

// ---------------------------------------------------------------------------
// Input order: 0 src, then (eW,eU,eb)x3, (dW,dU,db)x3, fW, fb
// ---------------------------------------------------------------------------
extern "C" void kernel_launch(void* const* d_in, const int* in_sizes, int n_in,
                              void* d_out, int out_size)
{
    const float* src = (const float*)d_in[0];
    const float* eW0 = (const float*)d_in[1];
    const float* eU0 = (const float*)d_in[2];
    const float* eb0 = (const float*)d_in[3];
    const float* eW1 = (const float*)d_in[4];
    const float* eU1 = (const float*)d_in[5];
    const float* eb1 = (const float*)d_in[6];
    const float* eW2 = (const float*)d_in[7];
    const float* eU2 = (const float*)d_in[8];
    const float* eb2 = (const float*)d_in[9];
    const float* dW0 = (const float*)d_in[10];
    const float* dU0 = (const float*)d_in[11];
    const float* db0 = (const float*)d_in[12];
    const float* dW1 = (const float*)d_in[13];
    const float* dU1 = (const float*)d_in[14];
    const float* db1 = (const float*)d_in[15];
    const float* dW2 = (const float*)d_in[16];
    const float* dU2 = (const float*)d_in[17];
    const float* db2 = (const float*)d_in[18];
    const float* fW  = (const float*)d_in[19];
    const float* fb  = (const float*)d_in[20];
    float* out = (float*)d_out;

    cudaFuncSetAttribute(lstm_main, cudaFuncAttributeMaxDynamicSharedMemorySize,
                         SMEM_BYTES);

    prep_kernel<<<1024, 256>>>(eW0, eU0, eW1, eU1, eW2, eU2,
                               dW0, dU0, dW1, dU1, dW2, dU2, fW);
    lstm_main<<<NBLK, NTHR, SMEM_BYTES>>>(src, eb0, eb1, eb2,
                                          db0, db1, db2, fb, out);
}

// round 6
// speedup vs baseline: 1.5437x; 1.0336x over previous
#include <cuda_runtime.h>

#define BATCH 2048
#define TSEQ  100
#define DVAR  51
#define HID   128
#define G4    512
#define RPB   14      // batch rows per block
#define XTS   18      // padded stride for state buffers [128][XTS]
#define WSZ   (256*512)
#define NBLK  147
#define NTHR  512

// gate buffer geometry: [rp 0..6][c 0..3][t 0..127][2], c-stride padded
#define GB_C   264                 /* floats per c-slot (128*2 + 8 pad) */
#define GB_RP  (4*GB_C)            /* 1056 floats per rp */
#define GBUF   (7*GB_RP)           /* one set's buffer: 7392 floats */

#define SMEM_FLOATS (7*128*XTS + 4*GBUF)   /* 16128 + 29568 = 45696 */
#define SMEM_BYTES  (SMEM_FLOATS*4)

// Transposed weights: per layer [256][512]; rows [0,128) = Wih^T (zero-padded),
// rows [128,256) = Whh^T. 8-row pad for unguarded prefetch.
__device__ float g_wt[6*WSZ + 8*G4];
// fW^T padded: [128][64], cols >= 51 zero
__device__ float g_fwt[128*64];

typedef unsigned long long ull;

__device__ __forceinline__ ull dup2(float x) {
    ull r; asm("mov.b64 %0, {%1, %1};" : "=l"(r) : "f"(x)); return r;
}
__device__ __forceinline__ void fma2(ull& d, ull a, ull b) {
    asm("fma.rn.f32x2 %0, %1, %2, %0;" : "+l"(d) : "l"(a), "l"(b));
}
__device__ __forceinline__ void pfL1(const float* p) {
    asm volatile("prefetch.global.L1 [%0];" :: "l"(p));
}
__device__ __forceinline__ float sigf(float x) {
    return __fdividef(1.0f, 1.0f + __expf(-x));
}
__device__ __forceinline__ float tanhff(float x) {
    float e = __expf(2.0f * x);
    return 1.0f - __fdividef(2.0f, e + 1.0f);
}

// ---------------------------------------------------------------------------
// Prep: transpose all LSTM weights (and fW) into g_wt / g_fwt
// ---------------------------------------------------------------------------
__global__ void prep_kernel(
    const float* w0, const float* u0, const float* w1, const float* u1,
    const float* w2, const float* u2, const float* w3, const float* u3,
    const float* w4, const float* u4, const float* w5, const float* u5,
    const float* fW)
{
    const float* WIH[6] = {w0, w1, w2, w3, w4, w5};
    const float* WHH[6] = {u0, u1, u2, u3, u4, u5};
    const int total = 6*WSZ + 8*G4 + 128*64;
    for (int idx = blockIdx.x*blockDim.x + threadIdx.x; idx < total;
         idx += gridDim.x*blockDim.x) {
        if (idx < 6*WSZ) {
            int layer = idx / WSZ;
            int rem   = idx - layer*WSZ;
            int k = rem >> 9;
            int j = rem & 511;
            int din = (layer == 0 || layer == 3) ? DVAR : HID;
            float v;
            if (k < 128) v = (k < din) ? WIH[layer][j*din + k] : 0.0f;
            else         v = WHH[layer][j*HID + (k - 128)];
            g_wt[idx] = v;
        } else if (idx < 6*WSZ + 8*G4) {
            g_wt[idx] = 0.0f;                 // prefetch pad
        } else {
            int r2 = idx - (6*WSZ + 8*G4);
            int u = r2 >> 6;
            int d = r2 & 63;
            g_fwt[r2] = (d < DVAR) ? fW[d*HID + u] : 0.0f;
        }
    }
}

// one k-step: 7 batched LDS.64 xp, then 4 gate-col FMA groups with a single
// live dup'd w-ull (low register pressure -> ptxas can hoist the loads)
__device__ __forceinline__ void kstep(float4 cur, const float* xk, ull* acc)
{
    ull xp[7];
#pragma unroll
    for (int rp = 0; rp < 7; rp++) xp[rp] = *(const ull*)(xk + 2*rp);
    ull w;
    w = dup2(cur.x);
#pragma unroll
    for (int rp = 0; rp < 7; rp++) fma2(acc[rp], xp[rp], w);
    w = dup2(cur.y);
#pragma unroll
    for (int rp = 0; rp < 7; rp++) fma2(acc[7+rp], xp[rp], w);
    w = dup2(cur.z);
#pragma unroll
    for (int rp = 0; rp < 7; rp++) fma2(acc[14+rp], xp[rp], w);
    w = dup2(cur.w);
#pragma unroll
    for (int rp = 0; rp < 7; rp++) fma2(acc[21+rp], xp[rp], w);
}

// ---------------------------------------------------------------------------
// GEMM partial over a k-range. W[4] carries the 4-deep LDG.128 pipeline
// across calls; the peeled last group prefetches rows 0..3 of `wnext`.
// ---------------------------------------------------------------------------
template<int K>
__device__ __forceinline__ void gpart(const float* __restrict__ wp,
                                      const float* xin, ull* acc,
                                      float4* W, const float* __restrict__ wnext)
{
#pragma unroll 1
    for (int kg = 0; kg < K/4 - 1; kg++) {
#pragma unroll
        for (int q = 0; q < 4; q++) {
            float4 cur = W[q];
            W[q] = *(const float4*)(wp + (4*kg + 4 + q)*G4);
            kstep(cur, xin + (4*kg + q)*XTS, acc);
        }
    }
#pragma unroll
    for (int q = 0; q < 4; q++) {           // peeled last group
        float4 cur = W[q];
        W[q] = *(const float4*)(wnext + q*G4);
        kstep(cur, xin + (K - 4 + q)*XTS, acc);
    }
}

// ---------------------------------------------------------------------------
// One LSTM cell, k-split across four 128-thread sets (4 gate cols/thread).
// wnext/knext: next cell's weight base + its per-set k-count, for L1 prefetch.
// ---------------------------------------------------------------------------
template<int KIN>
__device__ __noinline__ void cell(const float* __restrict__ wt,
                                  const float* __restrict__ bias,
                                  const float* xin, float* h, float* c,
                                  float* gb, int tid,
                                  const float* __restrict__ wnext, int knext)
{
    const int set = tid >> 7;            // 0..3
    const int t   = tid & 127;
    const int j0  = t << 2;              // 4-col base
    constexpr int KA = KIN/4;

    const float* wpA = wt + (set*KA)*G4 + j0;
    const float* wpB = wt + (128 + set*32)*G4 + j0;

    float4 W[4];
#pragma unroll
    for (int q = 0; q < 4; q++) W[q] = *(const float4*)(wpA + q*G4);

    ull acc[28];
    if (set == 0) {
        float4 bv = *(const float4*)(bias + j0);
#pragma unroll
        for (int rp = 0; rp < 7; rp++) {
            acc[rp] = dup2(bv.x); acc[7+rp] = dup2(bv.y);
            acc[14+rp] = dup2(bv.z); acc[21+rp] = dup2(bv.w);
        }
    } else {
#pragma unroll
        for (int i = 0; i < 28; i++) acc[i] = 0ull;
    }

    gpart<KA>(wpA, xin + (set*KA)*XTS, acc, W, wpB);     // tail preloads h-part W
    gpart<32>(wpB, h + (set*32)*XTS, acc, W, wpB);       // tail reload: harmless

    float* gs = gb + set*GBUF;
#pragma unroll
    for (int cc = 0; cc < 4; cc++)
#pragma unroll
        for (int rp = 0; rp < 7; rp++)
            *(ull*)(gs + rp*GB_RP + cc*GB_C + t*2) = acc[cc*7 + rp];

    // warm next cell's first weight rows into L1 (hidden behind barrier + EW)
    {
        const float* pf = wnext + (set*knext)*G4 + j0;
#pragma unroll
        for (int q = 0; q < 4; q++) pfL1(pf + q*G4);
    }
    __syncthreads();

    // elementwise: 128 units x 7 row-pairs = 896 items over 512 threads
#pragma unroll
    for (int it = 0; it < 2; it++) {
        int idx = tid + it*NTHR;
        if (idx < 896) {
            int u  = idx & 127;
            int rp = idx >> 7;
            int cb = rp*GB_RP + (u & 3)*GB_C + (u >> 2)*2;
            float2 gi = {0.f, 0.f}, gf = {0.f, 0.f}, gg = {0.f, 0.f}, go = {0.f, 0.f};
#pragma unroll
            for (int s = 0; s < 4; s++) {
                const float* g = gb + s*GBUF + cb;
                float2 a = *(const float2*)(g      );
                float2 b = *(const float2*)(g +  64);
                float2 d = *(const float2*)(g + 128);
                float2 e = *(const float2*)(g + 192);
                gi.x += a.x; gi.y += a.y;
                gf.x += b.x; gf.y += b.y;
                gg.x += d.x; gg.y += d.y;
                go.x += e.x; go.y += e.y;
            }
            float2 cc2 = *(const float2*)(c + u*XTS + 2*rp);
            float2 cn, hn;
            cn.x = sigf(gf.x)*cc2.x + sigf(gi.x)*tanhff(gg.x);
            cn.y = sigf(gf.y)*cc2.y + sigf(gi.y)*tanhff(gg.y);
            hn.x = sigf(go.x)*tanhff(cn.x);
            hn.y = sigf(go.y)*tanhff(cn.y);
            *(float2*)(c + u*XTS + 2*rp) = cn;
            *(float2*)(h + u*XTS + 2*rp) = hn;
        }
    }
    __syncthreads();
}

// ---------------------------------------------------------------------------
// Main persistent kernel: each block owns 14 batch rows, runs full enc+dec.
// ---------------------------------------------------------------------------
__global__ void __launch_bounds__(NTHR, 1) lstm_main(
    const float* __restrict__ src,
    const float* __restrict__ eb0, const float* __restrict__ eb1,
    const float* __restrict__ eb2,
    const float* __restrict__ db0, const float* __restrict__ db1,
    const float* __restrict__ db2,
    const float* __restrict__ fb,
    float* __restrict__ out)
{
    extern __shared__ float sm[];
    float* xt = sm;                        // [128][XTS]
    float* h0 = sm + 1*128*XTS;
    float* h1 = sm + 2*128*XTS;
    float* h2 = sm + 3*128*XTS;
    float* c0 = sm + 4*128*XTS;
    float* c1 = sm + 5*128*XTS;
    float* c2 = sm + 6*128*XTS;
    float* gb = sm + 7*128*XTS;            // 4 x GBUF

    const int tid = threadIdx.x;
    const int b0  = blockIdx.x * RPB;

    for (int i = tid; i < 7*128*XTS; i += NTHR) sm[i] = 0.0f;
    __syncthreads();

    // ----------------- encoder -----------------
    for (int t = 0; t < TSEQ; t++) {
        for (int i = tid; i < DVAR*RPB; i += NTHR) {
            int r = i / DVAR;
            int k = i - r*DVAR;
            int b = b0 + r; if (b >= BATCH) b = BATCH - 1;
            xt[k*XTS + r] = src[(b*TSEQ + t)*DVAR + k];
        }
        __syncthreads();
        cell<64 >(g_wt + 0*WSZ, eb0, xt, h0, c0, gb, tid, g_wt + 1*WSZ, 32);
        cell<128>(g_wt + 1*WSZ, eb1, h0, h1, c1, gb, tid, g_wt + 2*WSZ, 32);
        cell<128>(g_wt + 2*WSZ, eb2, h1, h2, c2, gb, tid,
                  (t < TSEQ-1) ? g_wt + 0*WSZ : g_wt + 3*WSZ, 16);
    }

    // ----------------- decoder -----------------
    for (int i = tid; i < 128*XTS; i += NTHR) xt[i] = 0.0f;   // x0 = zeros
    __syncthreads();

    for (int t = 0; t < TSEQ; t++) {
        cell<64 >(g_wt + 3*WSZ, db0, xt, h0, c0, gb, tid, g_wt + 4*WSZ, 32);
        cell<128>(g_wt + 4*WSZ, db1, h0, h1, c1, gb, tid, g_wt + 5*WSZ, 32);
        cell<128>(g_wt + 5*WSZ, db2, h1, h2, c2, gb, tid, g_wt + 3*WSZ, 16);

        // head: pred[r][d] = h2[r] . fW[d] + fb[d]; write out (reversed) + feedback
        {
            int d  = tid & 63;
            int rg = tid >> 6;                 // 0..7 ; rows rg and rg+8
            float fbv = (d < DVAR) ? fb[d] : 0.0f;
            float a0 = fbv, a1 = fbv;
            int r0 = rg, r1 = rg + 8;
#pragma unroll 4
            for (int u = 0; u < HID; u++) {
                float wv = g_fwt[(u << 6) + d];
                a0 += h2[u*XTS + r0] * wv;
                a1 += h2[u*XTS + r1] * wv;     // r1<=15 < XTS: in-bounds, guarded below
            }
            if (d < DVAR) {
                xt[d*XTS + r0] = a0;
                int bb = b0 + r0;
                if (bb < BATCH)
                    out[(bb*TSEQ + (TSEQ - 1 - t))*DVAR + d] = a0;
                if (r1 < RPB) {
                    xt[d*XTS + r1] = a1;
                    int bb1 = b0 + r1;
                    if (bb1 < BATCH)
                        out[(bb1*TSEQ + (TSEQ - 1 - t))*DVAR + d] = a1;
                }
            }
        }
        __syncthreads();
    }
}

// ---------------------------------------------------------------------------
// Input order: 0 src, then (eW,eU,eb)x3, (dW,dU,db)x3, fW, fb
// ---------------------------------------------------------------------------
extern "C" void kernel_launch(void* const* d_in, const int* in_sizes, int n_in,
                              void* d_out, int out_size)
{
    const float* src = (const float*)d_in[0];
    const float* eW0 = (const float*)d_in[1];
    const float* eU0 = (const float*)d_in[2];
    const float* eb0 = (const float*)d_in[3];
    const float* eW1 = (const float*)d_in[4];
    const float* eU1 = (const float*)d_in[5];
    const float* eb1 = (const float*)d_in[6];
    const float* eW2 = (const float*)d_in[7];
    const float* eU2 = (const float*)d_in[8];
    const float* eb2 = (const float*)d_in[9];
    const float* dW0 = (const float*)d_in[10];
    const float* dU0 = (const float*)d_in[11];
    const float* db0 = (const float*)d_in[12];
    const float* dW1 = (const float*)d_in[13];
    const float* dU1 = (const float*)d_in[14];
    const float* db1 = (const float*)d_in[15];
    const float* dW2 = (const float*)d_in[16];
    const float* dU2 = (const float*)d_in[17];
    const float* db2 = (const float*)d_in[18];
    const float* fW  = (const float*)d_in[19];
    const float* fb  = (const float*)d_in[20];
    float* out = (float*)d_out;

    cudaFuncSetAttribute(lstm_main, cudaFuncAttributeMaxDynamicSharedMemorySize,
                         SMEM_BYTES);

    prep_kernel<<<1024, 256>>>(eW0, eU0, eW1, eU1, eW2, eU2,
                               dW0, dU0, dW1, dU1, dW2, dU2, fW);
    lstm_main<<<NBLK, NTHR, SMEM_BYTES>>>(src, eb0, eb1, eb2,
                                          db0, db1, db2, fb, out);
}

// round 7
// speedup vs baseline: 1.5466x; 1.0019x over previous
#include <cuda_runtime.h>

#define BATCH 2048
#define TSEQ  100
#define DVAR  51
#define HID   128
#define G4    512
#define RPB   14      // batch rows per block
#define XTS   18      // padded stride for state buffers [128][XTS]
#define WSZ   (256*512)
#define NBLK  147
#define NTHR  512

// gate buffer geometry: [rp 0..6][c 0..3][t 0..127][2], c-stride padded
#define GB_C   264                 /* floats per c-slot (128*2 + 8 pad) */
#define GB_RP  (4*GB_C)            /* 1056 floats per rp */
#define GBUF   (7*GB_RP)           /* one set's buffer: 7392 floats */

#define SMEM_FLOATS (7*128*XTS + 4*GBUF)   /* 16128 + 29568 = 45696 */
#define SMEM_BYTES  (SMEM_FLOATS*4)

// Transposed weights: per layer [256][512]; rows [0,128) = Wih^T (zero-padded),
// rows [128,256) = Whh^T. 8-row pad for unguarded prefetch.
__device__ float g_wt[6*WSZ + 8*G4];
// fW^T padded: [128][64], cols >= 51 zero
__device__ float g_fwt[128*64];

typedef unsigned long long ull;

__device__ __forceinline__ ull dup2(float x) {
    ull r; asm("mov.b64 %0, {%1, %1};" : "=l"(r) : "f"(x)); return r;
}
__device__ __forceinline__ void fma2(ull& d, ull a, ull b) {
    asm("fma.rn.f32x2 %0, %1, %2, %0;" : "+l"(d) : "l"(a), "l"(b));
}
__device__ __forceinline__ void pfL1(const float* p) {
    asm volatile("prefetch.global.L1 [%0];" :: "l"(p));
}
__device__ __forceinline__ float sigf(float x) {
    return __fdividef(1.0f, 1.0f + __expf(-x));
}
__device__ __forceinline__ float tanhff(float x) {
    float e = __expf(2.0f * x);
    return 1.0f - __fdividef(2.0f, e + 1.0f);
}

// ---------------------------------------------------------------------------
// Prep: transpose all LSTM weights (and fW) into g_wt / g_fwt
// ---------------------------------------------------------------------------
__global__ void prep_kernel(
    const float* w0, const float* u0, const float* w1, const float* u1,
    const float* w2, const float* u2, const float* w3, const float* u3,
    const float* w4, const float* u4, const float* w5, const float* u5,
    const float* fW)
{
    const float* WIH[6] = {w0, w1, w2, w3, w4, w5};
    const float* WHH[6] = {u0, u1, u2, u3, u4, u5};
    const int total = 6*WSZ + 8*G4 + 128*64;
    for (int idx = blockIdx.x*blockDim.x + threadIdx.x; idx < total;
         idx += gridDim.x*blockDim.x) {
        if (idx < 6*WSZ) {
            int layer = idx / WSZ;
            int rem   = idx - layer*WSZ;
            int k = rem >> 9;
            int j = rem & 511;
            int din = (layer == 0 || layer == 3) ? DVAR : HID;
            float v;
            if (k < 128) v = (k < din) ? WIH[layer][j*din + k] : 0.0f;
            else         v = WHH[layer][j*HID + (k - 128)];
            g_wt[idx] = v;
        } else if (idx < 6*WSZ + 8*G4) {
            g_wt[idx] = 0.0f;                 // prefetch pad
        } else {
            int r2 = idx - (6*WSZ + 8*G4);
            int u = r2 >> 6;
            int d = r2 & 63;
            g_fwt[r2] = (d < DVAR) ? fW[d*HID + u] : 0.0f;
        }
    }
}

// one k-step: 7 batched LDS.64 xp, then 4 gate-col FMA groups with a single
// live dup'd w-ull (low register pressure -> ptxas can hoist the loads)
__device__ __forceinline__ void kstep(float4 cur, const float* xk, ull* acc)
{
    ull xp[7];
#pragma unroll
    for (int rp = 0; rp < 7; rp++) xp[rp] = *(const ull*)(xk + 2*rp);
    ull w;
    w = dup2(cur.x);
#pragma unroll
    for (int rp = 0; rp < 7; rp++) fma2(acc[rp], xp[rp], w);
    w = dup2(cur.y);
#pragma unroll
    for (int rp = 0; rp < 7; rp++) fma2(acc[7+rp], xp[rp], w);
    w = dup2(cur.z);
#pragma unroll
    for (int rp = 0; rp < 7; rp++) fma2(acc[14+rp], xp[rp], w);
    w = dup2(cur.w);
#pragma unroll
    for (int rp = 0; rp < 7; rp++) fma2(acc[21+rp], xp[rp], w);
}

// ---------------------------------------------------------------------------
// GEMM partial over a k-range. W[4] carries the 4-deep LDG.128 pipeline
// across calls; the peeled last group prefetches rows 0..3 of `wnext`.
// ---------------------------------------------------------------------------
template<int K>
__device__ __forceinline__ void gpart(const float* __restrict__ wp,
                                      const float* xin, ull* acc,
                                      float4* W, const float* __restrict__ wnext)
{
#pragma unroll 1
    for (int kg = 0; kg < K/4 - 1; kg++) {
#pragma unroll
        for (int q = 0; q < 4; q++) {
            float4 cur = W[q];
            W[q] = *(const float4*)(wp + (4*kg + 4 + q)*G4);
            kstep(cur, xin + (4*kg + q)*XTS, acc);
        }
    }
#pragma unroll
    for (int q = 0; q < 4; q++) {           // peeled last group
        float4 cur = W[q];
        W[q] = *(const float4*)(wnext + q*G4);
        kstep(cur, xin + (K - 4 + q)*XTS, acc);
    }
}

// ---------------------------------------------------------------------------
// One LSTM cell, k-split across four 128-thread sets (4 gate cols/thread).
// wnext/knext: next cell's weight base + its per-set k-count, for L1 prefetch.
// ---------------------------------------------------------------------------
template<int KIN>
__device__ __noinline__ void cell(const float* __restrict__ wt,
                                  const float* __restrict__ bias,
                                  const float* xin, float* h, float* c,
                                  float* gb, int tid,
                                  const float* __restrict__ wnext, int knext)
{
    const int set = tid >> 7;            // 0..3
    const int t   = tid & 127;
    const int j0  = t << 2;              // 4-col base
    constexpr int KA = KIN/4;

    const float* wpA = wt + (set*KA)*G4 + j0;
    const float* wpB = wt + (128 + set*32)*G4 + j0;

    float4 W[4];
#pragma unroll
    for (int q = 0; q < 4; q++) W[q] = *(const float4*)(wpA + q*G4);

    ull acc[28];
    if (set == 0) {
        float4 bv = *(const float4*)(bias + j0);
#pragma unroll
        for (int rp = 0; rp < 7; rp++) {
            acc[rp] = dup2(bv.x); acc[7+rp] = dup2(bv.y);
            acc[14+rp] = dup2(bv.z); acc[21+rp] = dup2(bv.w);
        }
    } else {
#pragma unroll
        for (int i = 0; i < 28; i++) acc[i] = 0ull;
    }

    gpart<KA>(wpA, xin + (set*KA)*XTS, acc, W, wpB);     // tail preloads h-part W
    gpart<32>(wpB, h + (set*32)*XTS, acc, W, wpB);       // tail reload: harmless

    float* gs = gb + set*GBUF;
#pragma unroll
    for (int cc = 0; cc < 4; cc++)
#pragma unroll
        for (int rp = 0; rp < 7; rp++)
            *(ull*)(gs + rp*GB_RP + cc*GB_C + t*2) = acc[cc*7 + rp];

    // warm next cell's first weight rows into L1 (hidden behind barrier + EW)
    {
        const float* pf = wnext + (set*knext)*G4 + j0;
#pragma unroll
        for (int q = 0; q < 4; q++) pfL1(pf + q*G4);
    }
    __syncthreads();

    // elementwise: 128 units x 7 row-pairs = 896 items over 512 threads
#pragma unroll
    for (int it = 0; it < 2; it++) {
        int idx = tid + it*NTHR;
        if (idx < 896) {
            int u  = idx & 127;
            int rp = idx >> 7;
            int cb = rp*GB_RP + (u & 3)*GB_C + (u >> 2)*2;
            float2 gi = {0.f, 0.f}, gf = {0.f, 0.f}, gg = {0.f, 0.f}, go = {0.f, 0.f};
#pragma unroll
            for (int s = 0; s < 4; s++) {
                const float* g = gb + s*GBUF + cb;
                float2 a = *(const float2*)(g      );
                float2 b = *(const float2*)(g +  64);
                float2 d = *(const float2*)(g + 128);
                float2 e = *(const float2*)(g + 192);
                gi.x += a.x; gi.y += a.y;
                gf.x += b.x; gf.y += b.y;
                gg.x += d.x; gg.y += d.y;
                go.x += e.x; go.y += e.y;
            }
            float2 cc2 = *(const float2*)(c + u*XTS + 2*rp);
            float2 cn, hn;
            cn.x = sigf(gf.x)*cc2.x + sigf(gi.x)*tanhff(gg.x);
            cn.y = sigf(gf.y)*cc2.y + sigf(gi.y)*tanhff(gg.y);
            hn.x = sigf(go.x)*tanhff(cn.x);
            hn.y = sigf(go.y)*tanhff(cn.y);
            *(float2*)(c + u*XTS + 2*rp) = cn;
            *(float2*)(h + u*XTS + 2*rp) = hn;
        }
    }
    __syncthreads();
}

// ---------------------------------------------------------------------------
// Main persistent kernel: each block owns 14 batch rows, runs full enc+dec.
// ---------------------------------------------------------------------------
__global__ void __launch_bounds__(NTHR, 1) lstm_main(
    const float* __restrict__ src,
    const float* __restrict__ eb0, const float* __restrict__ eb1,
    const float* __restrict__ eb2,
    const float* __restrict__ db0, const float* __restrict__ db1,
    const float* __restrict__ db2,
    const float* __restrict__ fb,
    float* __restrict__ out)
{
    extern __shared__ float sm[];
    float* xt = sm;                        // [128][XTS]
    float* h0 = sm + 1*128*XTS;
    float* h1 = sm + 2*128*XTS;
    float* h2 = sm + 3*128*XTS;
    float* c0 = sm + 4*128*XTS;
    float* c1 = sm + 5*128*XTS;
    float* c2 = sm + 6*128*XTS;
    float* gb = sm + 7*128*XTS;            // 4 x GBUF

    const int tid = threadIdx.x;
    const int b0  = blockIdx.x * RPB;

    for (int i = tid; i < 7*128*XTS; i += NTHR) sm[i] = 0.0f;
    __syncthreads();

    // ----------------- encoder -----------------
    for (int t = 0; t < TSEQ; t++) {
        for (int i = tid; i < DVAR*RPB; i += NTHR) {
            int r = i / DVAR;
            int k = i - r*DVAR;
            int b = b0 + r; if (b >= BATCH) b = BATCH - 1;
            xt[k*XTS + r] = src[(b*TSEQ + t)*DVAR + k];
        }
        __syncthreads();
        cell<64 >(g_wt + 0*WSZ, eb0, xt, h0, c0, gb, tid, g_wt + 1*WSZ, 32);
        cell<128>(g_wt + 1*WSZ, eb1, h0, h1, c1, gb, tid, g_wt + 2*WSZ, 32);
        cell<128>(g_wt + 2*WSZ, eb2, h1, h2, c2, gb, tid,
                  (t < TSEQ-1) ? g_wt + 0*WSZ : g_wt + 3*WSZ, 16);
    }

    // ----------------- decoder -----------------
    for (int i = tid; i < 128*XTS; i += NTHR) xt[i] = 0.0f;   // x0 = zeros
    __syncthreads();

    for (int t = 0; t < TSEQ; t++) {
        cell<64 >(g_wt + 3*WSZ, db0, xt, h0, c0, gb, tid, g_wt + 4*WSZ, 32);
        cell<128>(g_wt + 4*WSZ, db1, h0, h1, c1, gb, tid, g_wt + 5*WSZ, 32);
        cell<128>(g_wt + 5*WSZ, db2, h1, h2, c2, gb, tid, g_wt + 3*WSZ, 16);

        // head: pred[r][d] = h2[r] . fW[d] + fb[d]; write out (reversed) + feedback
        {
            int d  = tid & 63;
            int rg = tid >> 6;                 // 0..7 ; rows rg and rg+8
            float fbv = (d < DVAR) ? fb[d] : 0.0f;
            float a0 = fbv, a1 = fbv;
            int r0 = rg, r1 = rg + 8;
#pragma unroll 4
            for (int u = 0; u < HID; u++) {
                float wv = g_fwt[(u << 6) + d];
                a0 += h2[u*XTS + r0] * wv;
                a1 += h2[u*XTS + r1] * wv;     // r1<=15 < XTS: in-bounds, guarded below
            }
            if (d < DVAR) {
                xt[d*XTS + r0] = a0;
                int bb = b0 + r0;
                if (bb < BATCH)
                    out[(bb*TSEQ + (TSEQ - 1 - t))*DVAR + d] = a0;
                if (r1 < RPB) {
                    xt[d*XTS + r1] = a1;
                    int bb1 = b0 + r1;
                    if (bb1 < BATCH)
                        out[(bb1*TSEQ + (TSEQ - 1 - t))*DVAR + d] = a1;
                }
            }
        }
        __syncthreads();
    }
}

// ---------------------------------------------------------------------------
// Input order: 0 src, then (eW,eU,eb)x3, (dW,dU,db)x3, fW, fb
// ---------------------------------------------------------------------------
extern "C" void kernel_launch(void* const* d_in, const int* in_sizes, int n_in,
                              void* d_out, int out_size)
{
    const float* src = (const float*)d_in[0];
    const float* eW0 = (const float*)d_in[1];
    const float* eU0 = (const float*)d_in[2];
    const float* eb0 = (const float*)d_in[3];
    const float* eW1 = (const float*)d_in[4];
    const float* eU1 = (const float*)d_in[5];
    const float* eb1 = (const float*)d_in[6];
    const float* eW2 = (const float*)d_in[7];
    const float* eU2 = (const float*)d_in[8];
    const float* eb2 = (const float*)d_in[9];
    const float* dW0 = (const float*)d_in[10];
    const float* dU0 = (const float*)d_in[11];
    const float* db0 = (const float*)d_in[12];
    const float* dW1 = (const float*)d_in[13];
    const float* dU1 = (const float*)d_in[14];
    const float* db1 = (const float*)d_in[15];
    const float* dW2 = (const float*)d_in[16];
    const float* dU2 = (const float*)d_in[17];
    const float* db2 = (const float*)d_in[18];
    const float* fW  = (const float*)d_in[19];
    const float* fb  = (const float*)d_in[20];
    float* out = (float*)d_out;

    cudaFuncSetAttribute(lstm_main, cudaFuncAttributeMaxDynamicSharedMemorySize,
                         SMEM_BYTES);

    prep_kernel<<<1024, 256>>>(eW0, eU0, eW1, eU1, eW2, eU2,
                               dW0, dU0, dW1, dU1, dW2, dU2, fW);
    lstm_main<<<NBLK, NTHR, SMEM_BYTES>>>(src, eb0, eb1, eb2,
                                          db0, db1, db2, fb, out);
}

// round 8
// speedup vs baseline: 1.6056x; 1.0381x over previous
#include <cuda_runtime.h>

#define BATCH 2048
#define TSEQ  100
#define DVAR  51
#define HID   128
#define G4    512
#define RPB   14      // batch rows per block
#define XTS   18      // padded stride for state buffers [128][XTS]
#define WSZ   (256*512)
#define NBLK  147
#define NTHR  512

// gate buffer geometry: [rp 0..6][c 0..3][t 0..127][2], c-stride padded
#define GB_C   264                 /* floats per c-slot (128*2 + 8 pad) */
#define GB_RP  (4*GB_C)            /* 1056 floats per rp */
#define GBUF   (7*GB_RP)           /* one set's buffer: 7392 floats */

#define FWT_FLOATS (128*64)
#define SMEM_FLOATS (7*128*XTS + 4*GBUF + FWT_FLOATS) /* 16128+29568+8192 */
#define SMEM_BYTES  (SMEM_FLOATS*4)

// Transposed weights: per layer [256][512]; rows [0,128) = Wih^T (zero-padded),
// rows [128,256) = Whh^T. 8-row pad for unguarded prefetch.
__device__ float g_wt[6*WSZ + 8*G4];
// fW^T padded: [128][64], cols >= 51 zero
__device__ float g_fwt[FWT_FLOATS];

typedef unsigned long long ull;

__device__ __forceinline__ ull dup2(float x) {
    ull r; asm("mov.b64 %0, {%1, %1};" : "=l"(r) : "f"(x)); return r;
}
__device__ __forceinline__ void fma2(ull& d, ull a, ull b) {
    asm("fma.rn.f32x2 %0, %1, %2, %0;" : "+l"(d) : "l"(a), "l"(b));
}
__device__ __forceinline__ void pfL1(const float* p) {
    asm volatile("prefetch.global.L1 [%0];" :: "l"(p));
}
__device__ __forceinline__ float sigf(float x) {
    return __fdividef(1.0f, 1.0f + __expf(-x));
}
__device__ __forceinline__ float tanhff(float x) {
    float e = __expf(2.0f * x);
    return 1.0f - __fdividef(2.0f, e + 1.0f);
}

// ---------------------------------------------------------------------------
// Prep: transpose all LSTM weights (and fW) into g_wt / g_fwt
// ---------------------------------------------------------------------------
__global__ void prep_kernel(
    const float* w0, const float* u0, const float* w1, const float* u1,
    const float* w2, const float* u2, const float* w3, const float* u3,
    const float* w4, const float* u4, const float* w5, const float* u5,
    const float* fW)
{
    const float* WIH[6] = {w0, w1, w2, w3, w4, w5};
    const float* WHH[6] = {u0, u1, u2, u3, u4, u5};
    const int total = 6*WSZ + 8*G4 + FWT_FLOATS;
    for (int idx = blockIdx.x*blockDim.x + threadIdx.x; idx < total;
         idx += gridDim.x*blockDim.x) {
        if (idx < 6*WSZ) {
            int layer = idx / WSZ;
            int rem   = idx - layer*WSZ;
            int k = rem >> 9;
            int j = rem & 511;
            int din = (layer == 0 || layer == 3) ? DVAR : HID;
            float v;
            if (k < 128) v = (k < din) ? WIH[layer][j*din + k] : 0.0f;
            else         v = WHH[layer][j*HID + (k - 128)];
            g_wt[idx] = v;
        } else if (idx < 6*WSZ + 8*G4) {
            g_wt[idx] = 0.0f;                 // prefetch pad
        } else {
            int r2 = idx - (6*WSZ + 8*G4);
            int u = r2 >> 6;
            int d = r2 & 63;
            g_fwt[r2] = (d < DVAR) ? fW[d*HID + u] : 0.0f;
        }
    }
}

// One k-step: consume xv (loaded one k earlier), refill xv from xk (row k+1).
// Only one temp + 4 dup'd w ulls live -> low pressure, LDS latency hidden.
__device__ __forceinline__ void kstep(float4 cur, const float* xk,
                                      ull* acc, ull* xv)
{
    ull w0 = dup2(cur.x), w1 = dup2(cur.y), w2 = dup2(cur.z), w3 = dup2(cur.w);
#pragma unroll
    for (int rp = 0; rp < 7; rp++) {
        ull t = xv[rp];
        xv[rp] = *(const ull*)(xk + 2*rp);   // prefetch x row k+1 (LDS.64 bcast)
        fma2(acc[rp],      t, w0);
        fma2(acc[7 + rp],  t, w1);
        fma2(acc[14 + rp], t, w2);
        fma2(acc[21 + rp], t, w3);
    }
}

// ---------------------------------------------------------------------------
// GEMM partial over a k-range. W[4] carries the 4-deep LDG.128 pipeline
// (peeled tail prefetches wnext rows 0..3); xv[7] carries the x row pipeline
// (tail prefetches xnext row 0).
// ---------------------------------------------------------------------------
template<int K>
__device__ __forceinline__ void gpart(const float* __restrict__ wp,
                                      const float* xin, const float* xnext,
                                      ull* acc, ull* xv, float4* W,
                                      const float* __restrict__ wnext)
{
#pragma unroll 1
    for (int kg = 0; kg < K/4 - 1; kg++) {
#pragma unroll
        for (int q = 0; q < 4; q++) {
            const int k = 4*kg + q;
            float4 cur = W[q];
            W[q] = *(const float4*)(wp + (k + 4)*G4);
            kstep(cur, xin + (k + 1)*XTS, acc, xv);
        }
    }
#pragma unroll
    for (int q = 0; q < 4; q++) {           // peeled last group
        const int k = K - 4 + q;
        float4 cur = W[q];
        W[q] = *(const float4*)(wnext + q*G4);
        kstep(cur, (q == 3) ? xnext : xin + (k + 1)*XTS, acc, xv);
    }
}

// ---------------------------------------------------------------------------
// One LSTM cell, k-split across four 128-thread sets (4 gate cols/thread).
// wnext/knext: next cell's weight base + per-set k-count, for L1 prefetch.
// ---------------------------------------------------------------------------
template<int KIN>
__device__ __noinline__ void cell(const float* __restrict__ wt,
                                  const float* __restrict__ bias,
                                  const float* xin, float* h, float* c,
                                  float* gb, int tid,
                                  const float* __restrict__ wnext, int knext)
{
    const int set = tid >> 7;            // 0..3
    const int t   = tid & 127;
    const int j0  = t << 2;              // 4-col base
    constexpr int KA = KIN/4;

    const float* wpA = wt + (set*KA)*G4 + j0;
    const float* wpB = wt + (128 + set*32)*G4 + j0;
    const float* xA  = xin + (set*KA)*XTS;
    const float* xB  = h + (set*32)*XTS;

    float4 W[4];
#pragma unroll
    for (int q = 0; q < 4; q++) W[q] = *(const float4*)(wpA + q*G4);
    ull xv[7];
#pragma unroll
    for (int rp = 0; rp < 7; rp++) xv[rp] = *(const ull*)(xA + 2*rp);

    ull acc[28];
    if (set == 0) {
        float4 bv = *(const float4*)(bias + j0);
#pragma unroll
        for (int rp = 0; rp < 7; rp++) {
            acc[rp] = dup2(bv.x); acc[7+rp] = dup2(bv.y);
            acc[14+rp] = dup2(bv.z); acc[21+rp] = dup2(bv.w);
        }
    } else {
#pragma unroll
        for (int i = 0; i < 28; i++) acc[i] = 0ull;
    }

    gpart<KA>(wpA, xA, xB, acc, xv, W, wpB);   // tail preloads h-part W + h row 0
    gpart<32>(wpB, xB, xB, acc, xv, W, wpB);   // tail reloads: harmless

    float* gs = gb + set*GBUF;
#pragma unroll
    for (int cc = 0; cc < 4; cc++)
#pragma unroll
        for (int rp = 0; rp < 7; rp++)
            *(ull*)(gs + rp*GB_RP + cc*GB_C + t*2) = acc[cc*7 + rp];

    // warm next cell's first weight rows into L1 (hidden behind barrier + EW)
    {
        const float* pf = wnext + (set*knext)*G4 + j0;
#pragma unroll
        for (int q = 0; q < 4; q++) pfL1(pf + q*G4);
    }
    __syncthreads();

    // elementwise: 128 units x 7 row-pairs = 896 items over 512 threads
#pragma unroll
    for (int it = 0; it < 2; it++) {
        int idx = tid + it*NTHR;
        if (idx < 896) {
            int u  = idx & 127;
            int rp = idx >> 7;
            int cb = rp*GB_RP + (u & 3)*GB_C + (u >> 2)*2;
            float2 gi = {0.f, 0.f}, gf = {0.f, 0.f}, gg = {0.f, 0.f}, go = {0.f, 0.f};
#pragma unroll
            for (int s = 0; s < 4; s++) {
                const float* g = gb + s*GBUF + cb;
                float2 a = *(const float2*)(g      );
                float2 b = *(const float2*)(g +  64);
                float2 d = *(const float2*)(g + 128);
                float2 e = *(const float2*)(g + 192);
                gi.x += a.x; gi.y += a.y;
                gf.x += b.x; gf.y += b.y;
                gg.x += d.x; gg.y += d.y;
                go.x += e.x; go.y += e.y;
            }
            float2 cc2 = *(const float2*)(c + u*XTS + 2*rp);
            float2 cn, hn;
            cn.x = sigf(gf.x)*cc2.x + sigf(gi.x)*tanhff(gg.x);
            cn.y = sigf(gf.y)*cc2.y + sigf(gi.y)*tanhff(gg.y);
            hn.x = sigf(go.x)*tanhff(cn.x);
            hn.y = sigf(go.y)*tanhff(cn.y);
            *(float2*)(c + u*XTS + 2*rp) = cn;
            *(float2*)(h + u*XTS + 2*rp) = hn;
        }
    }
    __syncthreads();
}

// ---------------------------------------------------------------------------
// Main persistent kernel: each block owns 14 batch rows, runs full enc+dec.
// ---------------------------------------------------------------------------
__global__ void __launch_bounds__(NTHR, 1) lstm_main(
    const float* __restrict__ src,
    const float* __restrict__ eb0, const float* __restrict__ eb1,
    const float* __restrict__ eb2,
    const float* __restrict__ db0, const float* __restrict__ db1,
    const float* __restrict__ db2,
    const float* __restrict__ fb,
    float* __restrict__ out)
{
    extern __shared__ float sm[];
    float* xt   = sm;                        // [128][XTS]
    float* h0   = sm + 1*128*XTS;
    float* h1   = sm + 2*128*XTS;
    float* h2   = sm + 3*128*XTS;
    float* c0   = sm + 4*128*XTS;
    float* c1   = sm + 5*128*XTS;
    float* c2   = sm + 6*128*XTS;
    float* gb   = sm + 7*128*XTS;            // 4 x GBUF
    float* fwts = gb + 4*GBUF;               // [128][64] fW^T

    const int tid = threadIdx.x;
    const int b0  = blockIdx.x * RPB;

    for (int i = tid; i < 7*128*XTS; i += NTHR) sm[i] = 0.0f;
    for (int i = tid; i < FWT_FLOATS; i += NTHR) fwts[i] = g_fwt[i];
    __syncthreads();

    // ----------------- encoder -----------------
    for (int t = 0; t < TSEQ; t++) {
        for (int i = tid; i < DVAR*RPB; i += NTHR) {
            int r = i / DVAR;
            int k = i - r*DVAR;
            int b = b0 + r; if (b >= BATCH) b = BATCH - 1;
            xt[k*XTS + r] = src[(b*TSEQ + t)*DVAR + k];
        }
        __syncthreads();
        cell<64 >(g_wt + 0*WSZ, eb0, xt, h0, c0, gb, tid, g_wt + 1*WSZ, 32);
        cell<128>(g_wt + 1*WSZ, eb1, h0, h1, c1, gb, tid, g_wt + 2*WSZ, 32);
        cell<128>(g_wt + 2*WSZ, eb2, h1, h2, c2, gb, tid,
                  (t < TSEQ-1) ? g_wt + 0*WSZ : g_wt + 3*WSZ, 16);
    }

    // ----------------- decoder -----------------
    for (int i = tid; i < 128*XTS; i += NTHR) xt[i] = 0.0f;   // x0 = zeros
    __syncthreads();

    for (int t = 0; t < TSEQ; t++) {
        cell<64 >(g_wt + 3*WSZ, db0, xt, h0, c0, gb, tid, g_wt + 4*WSZ, 32);
        cell<128>(g_wt + 4*WSZ, db1, h0, h1, c1, gb, tid, g_wt + 5*WSZ, 32);
        cell<128>(g_wt + 5*WSZ, db2, h1, h2, c2, gb, tid, g_wt + 3*WSZ, 16);

        // head: pred[r][d] = h2[r] . fW[d] + fb[d]; write out (reversed) + feedback
        {
            int d  = tid & 63;
            int rg = tid >> 6;                 // 0..7 ; rows rg and rg+8
            float fbv = (d < DVAR) ? fb[d] : 0.0f;
            float a0 = fbv, a1 = fbv;
            int r0 = rg, r1 = rg + 8;
#pragma unroll 4
            for (int u = 0; u < HID; u++) {
                float wv = fwts[(u << 6) + d];
                a0 += h2[u*XTS + r0] * wv;
                a1 += h2[u*XTS + r1] * wv;     // r1<=15 < XTS: in-bounds, guarded below
            }
            if (d < DVAR) {
                xt[d*XTS + r0] = a0;
                int bb = b0 + r0;
                if (bb < BATCH)
                    out[(bb*TSEQ + (TSEQ - 1 - t))*DVAR + d] = a0;
                if (r1 < RPB) {
                    xt[d*XTS + r1] = a1;
                    int bb1 = b0 + r1;
                    if (bb1 < BATCH)
                        out[(bb1*TSEQ + (TSEQ - 1 - t))*DVAR + d] = a1;
                }
            }
        }
        __syncthreads();
    }
}

// ---------------------------------------------------------------------------
// Input order: 0 src, then (eW,eU,eb)x3, (dW,dU,db)x3, fW, fb
// ---------------------------------------------------------------------------
extern "C" void kernel_launch(void* const* d_in, const int* in_sizes, int n_in,
                              void* d_out, int out_size)
{
    const float* src = (const float*)d_in[0];
    const float* eW0 = (const float*)d_in[1];
    const float* eU0 = (const float*)d_in[2];
    const float* eb0 = (const float*)d_in[3];
    const float* eW1 = (const float*)d_in[4];
    const float* eU1 = (const float*)d_in[5];
    const float* eb1 = (const float*)d_in[6];
    const float* eW2 = (const float*)d_in[7];
    const float* eU2 = (const float*)d_in[8];
    const float* eb2 = (const float*)d_in[9];
    const float* dW0 = (const float*)d_in[10];
    const float* dU0 = (const float*)d_in[11];
    const float* db0 = (const float*)d_in[12];
    const float* dW1 = (const float*)d_in[13];
    const float* dU1 = (const float*)d_in[14];
    const float* db1 = (const float*)d_in[15];
    const float* dW2 = (const float*)d_in[16];
    const float* dU2 = (const float*)d_in[17];
    const float* db2 = (const float*)d_in[18];
    const float* fW  = (const float*)d_in[19];
    const float* fb  = (const float*)d_in[20];
    float* out = (float*)d_out;

    cudaFuncSetAttribute(lstm_main, cudaFuncAttributeMaxDynamicSharedMemorySize,
                         SMEM_BYTES);

    prep_kernel<<<1024, 256>>>(eW0, eU0, eW1, eU1, eW2, eU2,
                               dW0, dU0, dW1, dU1, dW2, dU2, fW);
    lstm_main<<<NBLK, NTHR, SMEM_BYTES>>>(src, eb0, eb1, eb2,
                                          db0, db1, db2, fb, out);
}

// round 9
// speedup vs baseline: 1.6177x; 1.0076x over previous
#include <cuda_runtime.h>

#define BATCH 2048
#define TSEQ  100
#define DVAR  51
#define HID   128
#define G4    512
#define RPB   14      // batch rows per block
#define XTS   18      // padded stride for state buffers [128][XTS]
#define WSZ   (256*512)
#define NBLK  147
#define NTHR  512

// gate buffer geometry: [rp 0..6][c 0..3][t 0..127][2], c-stride padded
#define GB_C   264                 /* floats per c-slot (128*2 + 8 pad) */
#define GB_RP  (4*GB_C)            /* 1056 floats per rp */
#define GBUF   (7*GB_RP)           /* one set's buffer: 7392 floats */

#define FWT_FLOATS (128*64)
#define SMEM_FLOATS (7*128*XTS + 4*GBUF + FWT_FLOATS) /* 16128+29568+8192 */
#define SMEM_BYTES  (SMEM_FLOATS*4)

// Transposed weights: per layer [256][512]; rows [0,128) = Wih^T (zero-padded),
// rows [128,256) = Whh^T. 8-row pad for unguarded prefetch.
__device__ float g_wt[6*WSZ + 8*G4];
// fW^T padded: [128][64], cols >= 51 zero
__device__ float g_fwt[FWT_FLOATS];

typedef unsigned long long ull;

__device__ __forceinline__ ull dup2(float x) {
    ull r; asm("mov.b64 %0, {%1, %1};" : "=l"(r) : "f"(x)); return r;
}
__device__ __forceinline__ void fma2(ull& d, ull a, ull b) {
    asm("fma.rn.f32x2 %0, %1, %2, %0;" : "+l"(d) : "l"(a), "l"(b));
}
__device__ __forceinline__ void pfL1(const float* p) {
    asm volatile("prefetch.global.L1 [%0];" :: "l"(p));
}
__device__ __forceinline__ float sigf(float x) {
    return __fdividef(1.0f, 1.0f + __expf(-x));
}
__device__ __forceinline__ float tanhff(float x) {
    float e = __expf(2.0f * x);
    return 1.0f - __fdividef(2.0f, e + 1.0f);
}

// ---------------------------------------------------------------------------
// Prep: transpose all LSTM weights (and fW) into g_wt / g_fwt
// ---------------------------------------------------------------------------
__global__ void prep_kernel(
    const float* w0, const float* u0, const float* w1, const float* u1,
    const float* w2, const float* u2, const float* w3, const float* u3,
    const float* w4, const float* u4, const float* w5, const float* u5,
    const float* fW)
{
    const float* WIH[6] = {w0, w1, w2, w3, w4, w5};
    const float* WHH[6] = {u0, u1, u2, u3, u4, u5};
    const int total = 6*WSZ + 8*G4 + FWT_FLOATS;
    for (int idx = blockIdx.x*blockDim.x + threadIdx.x; idx < total;
         idx += gridDim.x*blockDim.x) {
        if (idx < 6*WSZ) {
            int layer = idx / WSZ;
            int rem   = idx - layer*WSZ;
            int k = rem >> 9;
            int j = rem & 511;
            int din = (layer == 0 || layer == 3) ? DVAR : HID;
            float v;
            if (k < 128) v = (k < din) ? WIH[layer][j*din + k] : 0.0f;
            else         v = WHH[layer][j*HID + (k - 128)];
            g_wt[idx] = v;
        } else if (idx < 6*WSZ + 8*G4) {
            g_wt[idx] = 0.0f;                 // prefetch pad
        } else {
            int r2 = idx - (6*WSZ + 8*G4);
            int u = r2 >> 6;
            int d = r2 & 63;
            g_fwt[r2] = (d < DVAR) ? fW[d*HID + u] : 0.0f;
        }
    }
}

// One k-step, operand-reuse ordered: the 4 FMAs consuming xv[rp] are strictly
// back-to-back with x in the same operand slot (reuse cache -> rt2 for 3 of 4),
// reload of xv[rp] (for row k+1) happens after the quad.
__device__ __forceinline__ void kstep(float4 cur, const float* xk,
                                      ull* acc, ull* xv)
{
    ull w0 = dup2(cur.x), w1 = dup2(cur.y), w2 = dup2(cur.z), w3 = dup2(cur.w);
#pragma unroll
    for (int rp = 0; rp < 7; rp++) {
        fma2(acc[rp],      xv[rp], w0);
        fma2(acc[7 + rp],  xv[rp], w1);
        fma2(acc[14 + rp], xv[rp], w2);
        fma2(acc[21 + rp], xv[rp], w3);
        xv[rp] = *(const ull*)(xk + 2*rp);   // refill for row k+1 (LDS.64 bcast)
    }
}

// ---------------------------------------------------------------------------
// GEMM partial over a k-range. W[4] carries the 4-deep LDG.128 pipeline
// (peeled tail prefetches wnext rows 0..3); xv[7] carries the x row pipeline
// (tail prefetches xnext row 0).
// ---------------------------------------------------------------------------
template<int K>
__device__ __forceinline__ void gpart(const float* __restrict__ wp,
                                      const float* xin, const float* xnext,
                                      ull* acc, ull* xv, float4* W,
                                      const float* __restrict__ wnext)
{
#pragma unroll 1
    for (int kg = 0; kg < K/4 - 1; kg++) {
#pragma unroll
        for (int q = 0; q < 4; q++) {
            const int k = 4*kg + q;
            float4 cur = W[q];
            W[q] = *(const float4*)(wp + (k + 4)*G4);
            kstep(cur, xin + (k + 1)*XTS, acc, xv);
        }
    }
#pragma unroll
    for (int q = 0; q < 4; q++) {           // peeled last group
        const int k = K - 4 + q;
        float4 cur = W[q];
        W[q] = *(const float4*)(wnext + q*G4);
        kstep(cur, (q == 3) ? xnext : xin + (k + 1)*XTS, acc, xv);
    }
}

// ---------------------------------------------------------------------------
// One LSTM cell, k-split across four 128-thread sets (4 gate cols/thread).
// KA3: k-count for set 3 of the input GEMM (4 for input layers: k 51..63 of
// the zero-padded input contribute nothing, so set 3 runs only k 48..51).
// wnext/knext: next cell's weight base + per-set k-count, for L1 prefetch.
// ---------------------------------------------------------------------------
template<int KIN, int KA3>
__device__ __noinline__ void cell(const float* __restrict__ wt,
                                  const float* __restrict__ bias,
                                  const float* xin, float* h, float* c,
                                  float* gb, int tid,
                                  const float* __restrict__ wnext, int knext)
{
    const int set = tid >> 7;            // 0..3
    const int t   = tid & 127;
    const int j0  = t << 2;              // 4-col base
    constexpr int KA = KIN/4;
    const int kst = set*KA;

    const float* wpA = wt + kst*G4 + j0;
    const float* wpB = wt + (128 + set*32)*G4 + j0;
    const float* xA  = xin + kst*XTS;
    const float* xB  = h + (set*32)*XTS;

    float4 W[4];
#pragma unroll
    for (int q = 0; q < 4; q++) W[q] = *(const float4*)(wpA + q*G4);
    ull xv[7];
#pragma unroll
    for (int rp = 0; rp < 7; rp++) xv[rp] = *(const ull*)(xA + 2*rp);

    ull acc[28];
    if (set == 0) {
        float4 bv = *(const float4*)(bias + j0);
#pragma unroll
        for (int rp = 0; rp < 7; rp++) {
            acc[rp] = dup2(bv.x); acc[7+rp] = dup2(bv.y);
            acc[14+rp] = dup2(bv.z); acc[21+rp] = dup2(bv.w);
        }
    } else {
#pragma unroll
        for (int i = 0; i < 28; i++) acc[i] = 0ull;
    }

    if (KA3 == KA || set < 3) {
        gpart<KA>(wpA, xA, xB, acc, xv, W, wpB);   // tail preloads h-part W + h row 0
    } else {
        gpart<KA3>(wpA, xA, xB, acc, xv, W, wpB);  // set 3, input layer: skip zeros
    }
    gpart<32>(wpB, xB, xB, acc, xv, W, wpB);       // tail reloads: harmless

    float* gs = gb + set*GBUF;
#pragma unroll
    for (int cc = 0; cc < 4; cc++)
#pragma unroll
        for (int rp = 0; rp < 7; rp++)
            *(ull*)(gs + rp*GB_RP + cc*GB_C + t*2) = acc[cc*7 + rp];

    // warm next cell's first weight rows into L1 (hidden behind barrier + EW)
    {
        const float* pf = wnext + (set*knext)*G4 + j0;
#pragma unroll
        for (int q = 0; q < 4; q++) pfL1(pf + q*G4);
    }
    __syncthreads();

    // elementwise: 128 units x 7 row-pairs = 896 items over 512 threads
#pragma unroll
    for (int it = 0; it < 2; it++) {
        int idx = tid + it*NTHR;
        if (idx < 896) {
            int u  = idx & 127;
            int rp = idx >> 7;
            int cb = rp*GB_RP + (u & 3)*GB_C + (u >> 2)*2;
            float2 gi = {0.f, 0.f}, gf = {0.f, 0.f}, gg = {0.f, 0.f}, go = {0.f, 0.f};
#pragma unroll
            for (int s = 0; s < 4; s++) {
                const float* g = gb + s*GBUF + cb;
                float2 a = *(const float2*)(g      );
                float2 b = *(const float2*)(g +  64);
                float2 d = *(const float2*)(g + 128);
                float2 e = *(const float2*)(g + 192);
                gi.x += a.x; gi.y += a.y;
                gf.x += b.x; gf.y += b.y;
                gg.x += d.x; gg.y += d.y;
                go.x += e.x; go.y += e.y;
            }
            float2 cc2 = *(const float2*)(c + u*XTS + 2*rp);
            float2 cn, hn;
            cn.x = sigf(gf.x)*cc2.x + sigf(gi.x)*tanhff(gg.x);
            cn.y = sigf(gf.y)*cc2.y + sigf(gi.y)*tanhff(gg.y);
            hn.x = sigf(go.x)*tanhff(cn.x);
            hn.y = sigf(go.y)*tanhff(cn.y);
            *(float2*)(c + u*XTS + 2*rp) = cn;
            *(float2*)(h + u*XTS + 2*rp) = hn;
        }
    }
    __syncthreads();
}

// ---------------------------------------------------------------------------
// Main persistent kernel: each block owns 14 batch rows, runs full enc+dec.
// ---------------------------------------------------------------------------
__global__ void __launch_bounds__(NTHR, 1) lstm_main(
    const float* __restrict__ src,
    const float* __restrict__ eb0, const float* __restrict__ eb1,
    const float* __restrict__ eb2,
    const float* __restrict__ db0, const float* __restrict__ db1,
    const float* __restrict__ db2,
    const float* __restrict__ fb,
    float* __restrict__ out)
{
    extern __shared__ float sm[];
    float* xt   = sm;                        // [128][XTS]
    float* h0   = sm + 1*128*XTS;
    float* h1   = sm + 2*128*XTS;
    float* h2   = sm + 3*128*XTS;
    float* c0   = sm + 4*128*XTS;
    float* c1   = sm + 5*128*XTS;
    float* c2   = sm + 6*128*XTS;
    float* gb   = sm + 7*128*XTS;            // 4 x GBUF
    float* fwts = gb + 4*GBUF;               // [128][64] fW^T

    const int tid = threadIdx.x;
    const int b0  = blockIdx.x * RPB;

    for (int i = tid; i < 7*128*XTS; i += NTHR) sm[i] = 0.0f;
    for (int i = tid; i < FWT_FLOATS; i += NTHR) fwts[i] = g_fwt[i];
    __syncthreads();

    // ----------------- encoder -----------------
    for (int t = 0; t < TSEQ; t++) {
        for (int i = tid; i < DVAR*RPB; i += NTHR) {
            int r = i / DVAR;
            int k = i - r*DVAR;
            int b = b0 + r; if (b >= BATCH) b = BATCH - 1;
            xt[k*XTS + r] = src[(b*TSEQ + t)*DVAR + k];
        }
        __syncthreads();
        cell<64 , 4>(g_wt + 0*WSZ, eb0, xt, h0, c0, gb, tid, g_wt + 1*WSZ, 32);
        cell<128,32>(g_wt + 1*WSZ, eb1, h0, h1, c1, gb, tid, g_wt + 2*WSZ, 32);
        cell<128,32>(g_wt + 2*WSZ, eb2, h1, h2, c2, gb, tid,
                     (t < TSEQ-1) ? g_wt + 0*WSZ : g_wt + 3*WSZ, 16);
    }

    // ----------------- decoder -----------------
    for (int i = tid; i < 128*XTS; i += NTHR) xt[i] = 0.0f;   // x0 = zeros
    __syncthreads();

    for (int t = 0; t < TSEQ; t++) {
        cell<64 , 4>(g_wt + 3*WSZ, db0, xt, h0, c0, gb, tid, g_wt + 4*WSZ, 32);
        cell<128,32>(g_wt + 4*WSZ, db1, h0, h1, c1, gb, tid, g_wt + 5*WSZ, 32);
        cell<128,32>(g_wt + 5*WSZ, db2, h1, h2, c2, gb, tid, g_wt + 3*WSZ, 16);

        // head: pred[r][d] = h2[r] . fW[d] + fb[d]; write out (reversed) + feedback
        {
            int d  = tid & 63;
            int rg = tid >> 6;                 // 0..7 ; rows rg and rg+8
            float fbv = (d < DVAR) ? fb[d] : 0.0f;
            float a0 = fbv, a1 = fbv;
            int r0 = rg, r1 = rg + 8;
#pragma unroll 4
            for (int u = 0; u < HID; u++) {
                float wv = fwts[(u << 6) + d];
                a0 += h2[u*XTS + r0] * wv;
                a1 += h2[u*XTS + r1] * wv;     // r1<=15 < XTS: in-bounds, guarded below
            }
            if (d < DVAR) {
                xt[d*XTS + r0] = a0;
                int bb = b0 + r0;
                if (bb < BATCH)
                    out[(bb*TSEQ + (TSEQ - 1 - t))*DVAR + d] = a0;
                if (r1 < RPB) {
                    xt[d*XTS + r1] = a1;
                    int bb1 = b0 + r1;
                    if (bb1 < BATCH)
                        out[(bb1*TSEQ + (TSEQ - 1 - t))*DVAR + d] = a1;
                }
            }
        }
        __syncthreads();
    }
}

// ---------------------------------------------------------------------------
// Input order: 0 src, then (eW,eU,eb)x3, (dW,dU,db)x3, fW, fb
// ---------------------------------------------------------------------------
extern "C" void kernel_launch(void* const* d_in, const int* in_sizes, int n_in,
                              void* d_out, int out_size)
{
    const float* src = (const float*)d_in[0];
    const float* eW0 = (const float*)d_in[1];
    const float* eU0 = (const float*)d_in[2];
    const float* eb0 = (const float*)d_in[3];
    const float* eW1 = (const float*)d_in[4];
    const float* eU1 = (const float*)d_in[5];
    const float* eb1 = (const float*)d_in[6];
    const float* eW2 = (const float*)d_in[7];
    const float* eU2 = (const float*)d_in[8];
    const float* eb2 = (const float*)d_in[9];
    const float* dW0 = (const float*)d_in[10];
    const float* dU0 = (const float*)d_in[11];
    const float* db0 = (const float*)d_in[12];
    const float* dW1 = (const float*)d_in[13];
    const float* dU1 = (const float*)d_in[14];
    const float* db1 = (const float*)d_in[15];
    const float* dW2 = (const float*)d_in[16];
    const float* dU2 = (const float*)d_in[17];
    const float* db2 = (const float*)d_in[18];
    const float* fW  = (const float*)d_in[19];
    const float* fb  = (const float*)d_in[20];
    float* out = (float*)d_out;

    cudaFuncSetAttribute(lstm_main, cudaFuncAttributeMaxDynamicSharedMemorySize,
                         SMEM_BYTES);

    prep_kernel<<<1024, 256>>>(eW0, eU0, eW1, eU1, eW2, eU2,
                               dW0, dU0, dW1, dU1, dW2, dU2, fW);
    lstm_main<<<NBLK, NTHR, SMEM_BYTES>>>(src, eb0, eb1, eb2,
                                          db0, db1, db2, fb, out);
}